// round 11
// baseline (speedup 1.0000x reference)
#include <cuda_runtime.h>
#include <cuda_bf16.h>
#include <math.h>
#include <stdint.h>

// Problem constants
#define Bsz  2048
#define Tlen 200
#define Fdim 128
#define Hdim 256
#define Odim 6
#define G4H  1024
#define NC1  12          // 384/32
#define NC2  16          // 512/32
#define HW   (Hdim / 2)  // packed bf16x2 words per h row  (128)
#define XW   (Fdim / 2)  // packed words per x row          (64)
#define XSTR (Tlen * XW) // x packed row stride per batch

// ---------------------------------------------------------------------------
// Persistent device scratch. ALL batch-indexed arrays use SORTED row order
// (rows sorted by length descending; perm maps sorted -> original).
// ---------------------------------------------------------------------------
__device__ uint32_t g_h1h[2][Bsz * HW];
__device__ uint32_t g_h1l[2][Bsz * HW];
__device__ uint32_t g_h2h[2][Bsz * HW];
__device__ uint32_t g_h2l[2][Bsz * HW];
__device__ float    g_c1[Bsz * Hdim];
__device__ float    g_c2[Bsz * Hdim];
__device__ float    g_sum[Bsz * Hdim];
__device__ int      g_perm[Bsz];      // sorted row -> original row
__device__ int      g_lenS[Bsz];      // sorted lengths (descending)
__device__ int      g_nbArr[Tlen];    // active row-block count per step (16/8/4)
__device__ int      g_tgt[Tlen];      // cumulative per-block arrival target
__device__ int      g_trans[Tlen];    // 1 if nb changed vs previous step
__device__ unsigned g_ctr[16];        // per-row-block local barrier counters
__device__ unsigned g_bar;            // global barrier counter (transitions)

// Pre-split x (SORTED rows): packed bf16x2 words, layout [srow][t][f/2].
__device__ uint32_t g_xh[Bsz * Tlen * XW];
__device__ uint32_t g_xl[Bsz * Tlen * XW];

// Weights: gate-interleaved cols (h*4+g), bf16 hi/lo split, FRAGMENT-ordered:
// per (32-col strip s, chunk c): 1024 words = [hl][ks2][r][lane][nt]
__device__ uint32_t g_W1f[32 * NC1 * 1024];
__device__ uint32_t g_W2f[32 * NC2 * 1024];
__device__ float    g_b1r[G4H];
__device__ float    g_b2r[G4H];

// ---------------------------------------------------------------------------
// helpers
// ---------------------------------------------------------------------------
__device__ __forceinline__ float bfr(float a) {
    return __bfloat162float(__float2bfloat16(a));
}
__device__ __forceinline__ uint32_t packbf(float e0, float e1) {
    uint32_t d;
    asm("cvt.rn.bf16x2.f32 %0, %1, %2;" : "=r"(d) : "f"(e1), "f"(e0));
    return d;
}
__device__ __forceinline__ void mma_bf16(float* c, const uint32_t* a,
                                         const uint32_t* b) {
    asm volatile(
        "mma.sync.aligned.m16n8k16.row.col.f32.bf16.bf16.f32 "
        "{%0,%1,%2,%3}, {%4,%5,%6,%7}, {%8,%9}, {%0,%1,%2,%3};"
        : "+f"(c[0]), "+f"(c[1]), "+f"(c[2]), "+f"(c[3])
        : "r"(a[0]), "r"(a[1]), "r"(a[2]), "r"(a[3]), "r"(b[0]), "r"(b[1]));
}

#define CPASYNC16(dst, src) \
    asm volatile("cp.async.ca.shared.global [%0], [%1], 16;" :: "r"(dst), "l"(src))
#define CPASYNC16CG(dst, src) \
    asm volatile("cp.async.cg.shared.global [%0], [%1], 16;" :: "r"(dst), "l"(src))
#define CP_COMMIT() asm volatile("cp.async.commit_group;")
#define CP_WAIT0()  asm volatile("cp.async.wait_group 0;")

__device__ __forceinline__ float fast_sig(float v)  { return 1.0f / (1.0f + __expf(-v)); }
__device__ __forceinline__ float fast_tanh(float v) { return 1.0f - 2.0f / (__expf(2.0f * v) + 1.0f); }

// ---------------------------------------------------------------------------
// Prolog 1: sort rows by length desc (bitonic, deterministic, idx asc ties),
// build perm/lenS, the per-step schedule nbArr, the cumulative local-barrier
// targets tgt[t] = sum_{t'<=t} 128/nb(t') (block-independent because nb is
// monotone non-increasing), and transition flags.
// ---------------------------------------------------------------------------
__global__ void sort_kernel(const int* __restrict__ lengths)
{
    __shared__ unsigned key[Bsz];
    __shared__ int snb[Tlen];
    const int tid = threadIdx.x;       // 1024 threads
    key[tid]        = ((unsigned)(200 - lengths[tid]) << 11) | (unsigned)tid;
    key[tid + 1024] = ((unsigned)(200 - lengths[tid + 1024]) << 11)
                      | (unsigned)(tid + 1024);
    __syncthreads();
    for (int k = 2; k <= Bsz; k <<= 1) {
        for (int j = k >> 1; j > 0; j >>= 1) {
            const int i   = ((tid & ~(j - 1)) << 1) | (tid & (j - 1));
            const int par = i | j;
            const bool up = ((i & k) == 0);
            const unsigned a = key[i], b = key[par];
            if (up ? (a > b) : (a < b)) { key[i] = b; key[par] = a; }
            __syncthreads();
        }
    }
    for (int i = tid; i < Bsz; i += 1024) {
        g_perm[i] = (int)(key[i] & 2047u);
        g_lenS[i] = 200 - (int)(key[i] >> 11);
    }
    __syncthreads();
    if (tid < Tlen) {
        // R = #rows with len > tid  <=>  lower_bound of (200-tid)<<11
        const unsigned thr = (unsigned)(200 - tid) << 11;
        int lo = 0, hi = Bsz;
        while (lo < hi) {
            const int mid = (lo + hi) >> 1;
            if (key[mid] < thr) lo = mid + 1; else hi = mid;
        }
        const int cb = (lo + 127) >> 7;            // ceil(R/128)
        int nb = 4;
        while (nb < cb) nb <<= 1;                  // pow2ceil, min 4
        if (nb > 16) nb = 16;
        g_nbArr[tid] = nb;
        snb[tid] = nb;
    }
    __syncthreads();
    if (tid < Tlen) {
        int acc = 0;
        for (int tt = 0; tt <= tid; tt++) acc += 128 / snb[tt];
        g_tgt[tid]   = acc;
        g_trans[tid] = (tid > 0 && snb[tid] != snb[tid - 1]) ? 1 : 0;
    }
}

// ---------------------------------------------------------------------------
// Prolog 2: split x into packed bf16x2 hi/lo, permuted into sorted row order.
// ---------------------------------------------------------------------------
__global__ void split_x_kernel(const float* __restrict__ x)
{
    const int n2 = Bsz * (XSTR / 2);   // uint2 elements per dest
    for (int i = blockIdx.x * blockDim.x + threadIdx.x; i < n2;
         i += gridDim.x * blockDim.x) {
        const int srow = i / (XSTR / 2);
        const int rem  = i % (XSTR / 2);
        const int orow = g_perm[srow];
        float4 v = ((const float4*)x)[(size_t)orow * (XSTR / 2) + rem];
        uint2 wh, wl;
        wh.x = packbf(v.x, v.y);
        wh.y = packbf(v.z, v.w);
        wl.x = packbf(v.x - bfr(v.x), v.y - bfr(v.y));
        wl.y = packbf(v.z - bfr(v.z), v.w - bfr(v.w));
        ((uint2*)g_xh)[i] = wh;
        ((uint2*)g_xl)[i] = wl;
    }
}

// ---------------------------------------------------------------------------
// Prolog 3: weight reorder into fragment order + bf16 hi/lo split.
// ---------------------------------------------------------------------------
__global__ void reorder_frag(const float* __restrict__ W,
                             const float* __restrict__ bias,
                             int NC, int which)
{
    uint32_t* Wf = which ? g_W2f : g_W1f;
    float*    bd = which ? g_b2r : g_b1r;
    const int n = 32 * NC * 1024;
    for (int idx = blockIdx.x * blockDim.x + threadIdx.x; idx < n;
         idx += gridDim.x * blockDim.x) {
        int nt   = idx & 3;
        int lane = (idx >> 2) & 31;
        int r    = (idx >> 7) & 1;
        int ks2  = (idx >> 8) & 1;
        int hl   = (idx >> 9) & 1;
        int sc   = idx >> 10;
        int c    = sc % NC;
        int s    = sc / NC;

        int k0  = c * 32 + ks2 * 16 + r * 8 + 2 * (lane & 3);
        int col = s * 32 + nt * 8 + (lane >> 2);
        int h = col >> 2, g = col & 3;
        float w0 = W[k0 * G4H + g * Hdim + h];
        float w1 = W[(k0 + 1) * G4H + g * Hdim + h];
        Wf[idx] = (hl == 0)
            ? packbf(w0, w1)
            : packbf(w0 - bfr(w0), w1 - bfr(w1));

        if (idx < G4H) {
            int hh = idx >> 2, gg = idx & 3;
            bd[idx] = bias[gg * Hdim + hh];
        }
    }
}

__global__ void zero_kernel()
{
    const int idx = blockIdx.x * blockDim.x + threadIdx.x;
    if (idx == 0) g_bar = 0u;
    if (idx < 16) g_ctr[idx] = 0u;
    if (idx < Bsz * Hdim) {
        g_c1[idx] = 0.f; g_c2[idx] = 0.f; g_sum[idx] = 0.f;
    }
    if (idx < Bsz * HW) {
        g_h1h[0][idx] = 0u; g_h1l[0][idx] = 0u;
        g_h2h[0][idx] = 0u; g_h2l[0][idx] = 0u;
        g_h1h[1][idx] = 0u; g_h1l[1][idx] = 0u;
        g_h2h[1][idx] = 0u; g_h2l[1][idx] = 0u;
    }
}

// ---------------------------------------------------------------------------
// One layer phase, templated on LAYER and NB (active row blocks: 16/8/4).
// All 128 CTAs retile over the active prefix: STRIPS = 128/NB CTAs per block,
// each covering 8*NB gate columns. bf16 m16n8k16 3-term split GEMM with
// cp.async double buffer; fused LSTM cell epilogue; c/sum state in gmem
// (.cg, ownership migrates across steps). Rows past their length are simply
// masked (sorted order: once invalid, forever invalid; stale h is finite
// and feeds only masked outputs, so no copy-through is needed).
// ---------------------------------------------------------------------------
#define ASTR   20
#define A_LO_W 2560
#define B_W    5120
#define STGW   9216
#define STGB   (STGW * 4)          // 36864 B
#define SMEM_TOTAL (2 * STGB)      // 73728 B
#define ZSTR   132

template <int LAYER, int NB>
__device__ __forceinline__ void phase_fn(int t)
{
    constexpr int NC   = (LAYER == 1) ? NC1 : NC2;
    constexpr int W0C  = (LAYER == 1) ? 4 : 8;   // chunks from segment 0
    constexpr int NT   = NB / 4;     // n8 tiles per warp
    constexpr int STRN = NB / 4;     // 32-col weight strips per CTA
    constexpr int WPS  = 4 / NT;     // warps sharing one strip
    constexpr int STRIPS = 128 / NB; // CTAs per row block
    constexpr int UPT  = NB / 2;     // units per epilogue thread

    extern __shared__ uint32_t smw[];
    uint32_t smb;
    asm("{ .reg .u64 t0; cvta.to.shared.u64 t0, %1; cvt.u32.u64 %0, t0; }"
        : "=r"(smb) : "l"(smw));

    const uint32_t* __restrict__ Wf = (LAYER == 1) ? g_W1f : g_W2f;
    const float*    __restrict__ bd = (LAYER == 1) ? g_b1r : g_b2r;
    float* __restrict__ cst = (LAYER == 1) ? g_c1 : g_c2;

    const int tid  = threadIdx.x;
    const int lane = tid & 31;
    const int gq   = lane >> 2;
    const int rq   = lane & 3;
    const int wid  = tid >> 5;
    const int wr   = wid & 3;
    const int wcol = wid >> 2;
    const int rb   = blockIdx.x / STRIPS;
    const int cs   = blockIdx.x % STRIPS;
    const int row0 = rb * 128;
    const int col0 = cs * (8 * NB);
    const int sbase = cs * STRN;
    const int prow = tid >> 2;
    const int pq   = tid & 3;
    const int erow = tid >> 2;
    const int eub  = (tid & 3) * UPT;

    const int p = t & 1;
    const uint32_t* s0h; const uint32_t* s0l; size_t s0s, s0k;
    if (LAYER == 1) { s0h = g_xh; s0l = g_xl; s0s = XSTR; s0k = (size_t)t * XW; }
    else            { s0h = g_h1h[p ^ 1]; s0l = g_h1l[p ^ 1]; s0s = HW; s0k = 0; }
    const uint32_t* hph = (LAYER == 1) ? g_h1h[p] : g_h2h[p];
    const uint32_t* hpl = (LAYER == 1) ? g_h1l[p] : g_h2l[p];
    uint32_t* hnh = (LAYER == 1) ? g_h1h[p ^ 1] : g_h2h[p ^ 1];
    uint32_t* hnl = (LAYER == 1) ? g_h1l[p ^ 1] : g_h2l[p ^ 1];

    // ---- epilogue ownership + state prefetch (hidden under GEMM) ----
    const int rowg  = row0 + erow;
    const int mylen = g_lenS[rowg];
    const bool valid = (t < mylen);
    const int gu0 = (col0 >> 2) + eub;
    float creg[UPT], sumr[UPT];
    if (valid) {
#pragma unroll
        for (int u = 0; u < UPT; u++) {
            creg[u] = __ldcg(&cst[rowg * Hdim + gu0 + u]);
            if (LAYER == 2) sumr[u] = __ldcg(&g_sum[rowg * Hdim + gu0 + u]);
        }
    }

    auto fill = [&](int c) {
        const uint32_t sb = smb + (uint32_t)(c & 1) * STGB;
        size_t off; const uint32_t *ph, *pl;
        if (c < W0C) {
            ph = s0h; pl = s0l;
            off = (size_t)(row0 + prow) * s0s + s0k + c * 16 + pq * 4;
        } else {
            ph = hph; pl = hpl;
            off = (size_t)(row0 + prow) * HW + (c - W0C) * 16 + pq * 4;
        }
        const uint32_t adst = sb + (uint32_t)(prow * ASTR + pq * 4) * 4u;
        CPASYNC16CG(adst, ph + off);                 // .cg: no stale L1
        CPASYNC16CG(adst + A_LO_W * 4u, pl + off);
        // B: STRN strips * 1024 words; 16B per op
#pragma unroll
        for (int o = 0; o < (STRN * 256 + 511) / 512; o++) {
            const int oo = tid + o * 512;
            if ((STRN * 256 % 512 == 0) || (oo < STRN * 256)) {
                const int j = oo >> 8;
                const int w = (oo & 255) * 4;
                const uint32_t* src =
                    Wf + ((size_t)(sbase + j) * NC + c) * 1024 + w;
                CPASYNC16(sb + (uint32_t)(B_W + j * 1024 + w) * 4u, src);
            }
        }
    };

    float acc[2][NT][4];
#pragma unroll
    for (int mt = 0; mt < 2; mt++)
#pragma unroll
        for (int nt = 0; nt < NT; nt++)
#pragma unroll
            for (int q = 0; q < 4; q++) acc[mt][nt][q] = 0.0f;

    fill(0);
    CP_COMMIT();

#pragma unroll 1
    for (int c = 0; c < NC; c++) {
        CP_WAIT0();
        __syncthreads();
        if (c + 1 < NC) { fill(c + 1); CP_COMMIT(); }

        const uint32_t* ash = smw + (c & 1) * STGW;
        const uint32_t* asl = ash + A_LO_W;
        const uint32_t* bb  = ash + B_W + (wcol / WPS) * 1024
                            + (wcol % WPS) * NT;

#pragma unroll
        for (int ks2 = 0; ks2 < 2; ks2++) {
            uint32_t bh0[NT], bh1[NT], bl0[NT], bl1[NT];
            if (NT == 4) {
                *(uint4*)bh0 = *(const uint4*)(bb + ks2 * 256 + lane * 4);
                *(uint4*)bh1 = *(const uint4*)(bb + ks2 * 256 + 128 + lane * 4);
                *(uint4*)bl0 = *(const uint4*)(bb + 512 + ks2 * 256 + lane * 4);
                *(uint4*)bl1 = *(const uint4*)(bb + 512 + ks2 * 256 + 128 + lane * 4);
            } else if (NT == 2) {
                *(uint2*)bh0 = *(const uint2*)(bb + ks2 * 256 + lane * 4);
                *(uint2*)bh1 = *(const uint2*)(bb + ks2 * 256 + 128 + lane * 4);
                *(uint2*)bl0 = *(const uint2*)(bb + 512 + ks2 * 256 + lane * 4);
                *(uint2*)bl1 = *(const uint2*)(bb + 512 + ks2 * 256 + 128 + lane * 4);
            } else {
                bh0[0] = bb[ks2 * 256 + lane * 4];
                bh1[0] = bb[ks2 * 256 + 128 + lane * 4];
                bl0[0] = bb[512 + ks2 * 256 + lane * 4];
                bl1[0] = bb[512 + ks2 * 256 + 128 + lane * 4];
            }

            const int kw = ks2 * 8 + rq;
#pragma unroll
            for (int mt = 0; mt < 2; mt++) {
                const int r0 = wr * 32 + mt * 16 + gq;
                uint32_t ah[4], al[4];
                ah[0] = ash[r0 * ASTR + kw];
                ah[1] = ash[(r0 + 8) * ASTR + kw];
                ah[2] = ash[r0 * ASTR + kw + 4];
                ah[3] = ash[(r0 + 8) * ASTR + kw + 4];
                al[0] = asl[r0 * ASTR + kw];
                al[1] = asl[(r0 + 8) * ASTR + kw];
                al[2] = asl[r0 * ASTR + kw + 4];
                al[3] = asl[(r0 + 8) * ASTR + kw + 4];
#pragma unroll
                for (int nt = 0; nt < NT; nt++) {
                    uint32_t bhp[2] = { bh0[nt], bh1[nt] };
                    uint32_t blp[2] = { bl0[nt], bl1[nt] };
                    mma_bf16(acc[mt][nt], ah, bhp);
                    mma_bf16(acc[mt][nt], ah, blp);
                    mma_bf16(acc[mt][nt], al, bhp);
                }
            }
        }
    }
    __syncthreads();   // all compute done before Z overwrites stages

    // ---- stage Z in smem ----
    float* Zs = (float*)smw;
#pragma unroll
    for (int mt = 0; mt < 2; mt++)
#pragma unroll
        for (int nt = 0; nt < NT; nt++) {
            const int row = wr * 32 + mt * 16 + gq;
            const int col = wcol * (8 * NT) + nt * 8 + 2 * rq;
            Zs[row * ZSTR + col]           = acc[mt][nt][0];
            Zs[row * ZSTR + col + 1]       = acc[mt][nt][1];
            Zs[(row + 8) * ZSTR + col]     = acc[mt][nt][2];
            Zs[(row + 8) * ZSTR + col + 1] = acc[mt][nt][3];
        }
    __syncthreads();

    // ---- fused LSTM cell (valid rows only) ----
    if (valid) {
        const size_t hw0 = (size_t)rowg * HW + (gu0 >> 1);
#pragma unroll
        for (int u2 = 0; u2 < UPT / 2; u2++) {
            float nhv[2];
#pragma unroll
            for (int e = 0; e < 2; e++) {
                const int uu = 2 * u2 + e;
                const int n4 = (eub + uu) * 4;
                float4 z  = *(const float4*)&Zs[erow * ZSTR + n4];
                float4 bv = *(const float4*)&bd[col0 + n4];
                const float zi = z.x + bv.x;
                const float zj = z.y + bv.y;
                const float zf = z.z + bv.z;
                const float zo = z.w + bv.w;
                const float nc = creg[uu] * fast_sig(zf + 1.0f)
                               + fast_sig(zi) * fast_tanh(zj);
                const float nh = fast_tanh(nc) * fast_sig(zo);
                creg[uu] = nc;
                if (LAYER == 2) sumr[uu] += nh;
                nhv[e] = nh;
            }
            hnh[hw0 + u2] = packbf(nhv[0], nhv[1]);
            hnl[hw0 + u2] = packbf(nhv[0] - bfr(nhv[0]),
                                   nhv[1] - bfr(nhv[1]));
        }
#pragma unroll
        for (int u = 0; u < UPT; u++) {
            __stcg(&cst[rowg * Hdim + gu0 + u], creg[u]);
            if (LAYER == 2) __stcg(&g_sum[rowg * Hdim + gu0 + u], sumr[u]);
        }
    }
    __syncthreads();   // Z reads done before next phase's fill
}

// ---------------------------------------------------------------------------
// Persistent kernel: 128 CTAs, 200 steps x 2 layers.
// Per-step LOCAL row-block barrier (128/nb CTAs); GLOBAL barrier only at
// nb transitions (<=2 per run), where the CTA<->block mapping changes.
// ---------------------------------------------------------------------------
__global__ void __launch_bounds__(512, 1)
lstm_persist()
{
    const int tid = threadIdx.x;
    int ntrans = 0;

#pragma unroll 1
    for (int t = 0; t < Tlen; t++) {
        const int nb = g_nbArr[t];

        // Global barrier at nb transitions: CTA->row-block mapping changes,
        // so the previous step's writers are a different CTA set.
        if (t > 0 && g_trans[t]) {
            ntrans++;
            if (tid == 0) {
                unsigned* bp = &g_bar;
                asm volatile("red.release.gpu.add.u32 [%0], 1;" :: "l"(bp) : "memory");
                const unsigned tgt = 128u * (unsigned)ntrans;
                unsigned v;
                while (true) {
                    asm volatile("ld.acquire.gpu.b32 %0, [%1];"
                                 : "=r"(v) : "l"(bp) : "memory");
                    if (v >= tgt) break;
                    asm volatile("nanosleep.u32 128;");
                }
            }
            __syncthreads();
        }

        if (nb == 16)     phase_fn<1, 16>(t);
        else if (nb == 8) phase_fn<1, 8>(t);
        else              phase_fn<1, 4>(t);

        // Local row-block barrier (128/nb CTAs), cumulative target g_tgt[t].
        {
            const int strips = 128 / nb;
            if (tid == 0) {
                unsigned* bp = &g_ctr[blockIdx.x / strips];
                asm volatile("red.release.gpu.add.u32 [%0], 1;" :: "l"(bp) : "memory");
                const unsigned tgt = (unsigned)g_tgt[t];
                unsigned v;
                while (true) {
                    asm volatile("ld.acquire.gpu.b32 %0, [%1];"
                                 : "=r"(v) : "l"(bp) : "memory");
                    if (v >= tgt) break;
                    asm volatile("nanosleep.u32 64;");
                }
            }
            __syncthreads();
        }

        if (nb == 16)     phase_fn<2, 16>(t);
        else if (nb == 8) phase_fn<2, 8>(t);
        else              phase_fn<2, 4>(t);
    }
}

// ---------------------------------------------------------------------------
// logits[orig b, o] = dot(sum_sorted[srow,:], Wout[:,o]) / lenS[srow] + bout[o]
// ---------------------------------------------------------------------------
__global__ void final_kernel(const float* __restrict__ Wout,
                             const float* __restrict__ bout,
                             float* __restrict__ out)
{
    const int idx = blockIdx.x * blockDim.x + threadIdx.x;
    if (idx >= Bsz * Odim) return;
    const int srow = idx / Odim;
    const int o    = idx % Odim;
    const float* s = g_sum + srow * Hdim;
    float acc = 0.0f;
#pragma unroll 8
    for (int h = 0; h < Hdim; h++) acc += s[h] * Wout[h * Odim + o];
    out[g_perm[srow] * Odim + o] =
        acc / (float)g_lenS[srow] + bout[o];
}

// ---------------------------------------------------------------------------
// Inputs (metadata order): x, lengths, W1, b1, W2, b2, Wout, bout
// ---------------------------------------------------------------------------
extern "C" void kernel_launch(void* const* d_in, const int* in_sizes, int n_in,
                              void* d_out, int out_size)
{
    const float* x       = (const float*)d_in[0];
    const int*   lengths = (const int*)d_in[1];
    const float* W1      = (const float*)d_in[2];
    const float* b1      = (const float*)d_in[3];
    const float* W2      = (const float*)d_in[4];
    const float* b2      = (const float*)d_in[5];
    const float* Wout    = (const float*)d_in[6];
    const float* bout    = (const float*)d_in[7];
    float* out = (float*)d_out;

    cudaFuncSetAttribute(lstm_persist,
                         cudaFuncAttributeMaxDynamicSharedMemorySize, SMEM_TOTAL);

    sort_kernel<<<1, 1024>>>(lengths);
    split_x_kernel<<<4096, 256>>>(x);
    reorder_frag<<<1536, 256>>>(W1, b1, NC1, 0);
    reorder_frag<<<2048, 256>>>(W2, b2, NC2, 1);
    zero_kernel<<<2048, 256>>>();

    lstm_persist<<<128, 512, SMEM_TOTAL>>>();

    final_kernel<<<(Bsz * Odim + 255) / 256, 256>>>(Wout, bout, out);
}

// round 14
// speedup vs baseline: 1.0232x; 1.0232x over previous
#include <cuda_runtime.h>
#include <cuda_bf16.h>
#include <math.h>
#include <stdint.h>

// Problem constants
#define Bsz  2048
#define Tlen 200
#define Fdim 128
#define Hdim 256
#define Odim 6
#define G4H  1024
#define NC1  12          // 384/32
#define NC2  16          // 512/32
#define HW   (Hdim / 2)  // packed bf16x2 words per h row  (128)
#define XW   (Fdim / 2)  // packed words per x row          (64)
#define XSTR (Tlen * XW) // x packed row stride per batch

// ---------------------------------------------------------------------------
// Persistent device scratch. ALL batch-indexed arrays use SORTED row order
// (rows sorted by length descending; perm maps sorted -> original).
// ---------------------------------------------------------------------------
__device__ uint32_t g_h1h[2][Bsz * HW];
__device__ uint32_t g_h1l[2][Bsz * HW];
__device__ uint32_t g_h2h[2][Bsz * HW];
__device__ uint32_t g_h2l[2][Bsz * HW];
__device__ float    g_c1[Bsz * Hdim];
__device__ float    g_c2[Bsz * Hdim];
__device__ float    g_sum[Bsz * Hdim];
__device__ int      g_perm[Bsz];      // sorted row -> original row
__device__ int      g_lenS[Bsz];      // sorted lengths (descending)
__device__ int      g_nbArr[Tlen];    // active row-block count per step (16/8/4)
__device__ int      g_tgt[Tlen];      // cumulative per-block arrival target
__device__ int      g_trans[Tlen];    // 1 if nb changed vs previous step
__device__ unsigned g_ctr[16];        // per-row-block local barrier counters
__device__ unsigned g_bar;            // global barrier counter (transitions)

// Pre-split x (SORTED rows): packed bf16x2 words, layout [srow][t][f/2].
__device__ uint32_t g_xh[Bsz * Tlen * XW];
__device__ uint32_t g_xl[Bsz * Tlen * XW];

// Weights: gate-interleaved cols (h*4+g), bf16 hi/lo split, FRAGMENT-ordered:
// per (32-col strip s, chunk c): 1024 words = [hl][ks2][r][lane][nt]
__device__ uint32_t g_W1f[32 * NC1 * 1024];
__device__ uint32_t g_W2f[32 * NC2 * 1024];
__device__ float    g_b1r[G4H];
__device__ float    g_b2r[G4H];

// ---------------------------------------------------------------------------
// helpers
// ---------------------------------------------------------------------------
__device__ __forceinline__ float bfr(float a) {
    return __bfloat162float(__float2bfloat16(a));
}
__device__ __forceinline__ uint32_t packbf(float e0, float e1) {
    uint32_t d;
    asm("cvt.rn.bf16x2.f32 %0, %1, %2;" : "=r"(d) : "f"(e1), "f"(e0));
    return d;
}
__device__ __forceinline__ void mma_bf16(float* c, const uint32_t* a,
                                         const uint32_t* b) {
    asm volatile(
        "mma.sync.aligned.m16n8k16.row.col.f32.bf16.bf16.f32 "
        "{%0,%1,%2,%3}, {%4,%5,%6,%7}, {%8,%9}, {%0,%1,%2,%3};"
        : "+f"(c[0]), "+f"(c[1]), "+f"(c[2]), "+f"(c[3])
        : "r"(a[0]), "r"(a[1]), "r"(a[2]), "r"(a[3]), "r"(b[0]), "r"(b[1]));
}

// ldmatrix x4: loads the full m16k16 A fragment (4 regs) in one op.
#define LDSM_X4(r0, r1, r2, r3, addr) \
    asm volatile("ldmatrix.sync.aligned.m8n8.x4.shared.b16 {%0,%1,%2,%3}, [%4];" \
        : "=r"(r0), "=r"(r1), "=r"(r2), "=r"(r3) : "r"(addr))

#define CPASYNC16(dst, src) \
    asm volatile("cp.async.ca.shared.global [%0], [%1], 16;" :: "r"(dst), "l"(src))
#define CPASYNC16CG(dst, src) \
    asm volatile("cp.async.cg.shared.global [%0], [%1], 16;" :: "r"(dst), "l"(src))
#define CP_COMMIT() asm volatile("cp.async.commit_group;")
#define CP_WAIT0()  asm volatile("cp.async.wait_group 0;")

__device__ __forceinline__ float fast_sig(float v)  { return 1.0f / (1.0f + __expf(-v)); }
__device__ __forceinline__ float fast_tanh(float v) { return 1.0f - 2.0f / (__expf(2.0f * v) + 1.0f); }

// ---------------------------------------------------------------------------
// Prolog 1: sort rows by length desc (bitonic, deterministic, idx asc ties),
// build perm/lenS, the per-step schedule nbArr, the cumulative local-barrier
// targets tgt[t] = sum_{t'<=t} 128/nb(t'), and transition flags.
// ---------------------------------------------------------------------------
__global__ void sort_kernel(const int* __restrict__ lengths)
{
    __shared__ unsigned key[Bsz];
    __shared__ int snb[Tlen];
    const int tid = threadIdx.x;       // 1024 threads
    key[tid]        = ((unsigned)(200 - lengths[tid]) << 11) | (unsigned)tid;
    key[tid + 1024] = ((unsigned)(200 - lengths[tid + 1024]) << 11)
                      | (unsigned)(tid + 1024);
    __syncthreads();
    for (int k = 2; k <= Bsz; k <<= 1) {
        for (int j = k >> 1; j > 0; j >>= 1) {
            const int i   = ((tid & ~(j - 1)) << 1) | (tid & (j - 1));
            const int par = i | j;
            const bool up = ((i & k) == 0);
            const unsigned a = key[i], b = key[par];
            if (up ? (a > b) : (a < b)) { key[i] = b; key[par] = a; }
            __syncthreads();
        }
    }
    for (int i = tid; i < Bsz; i += 1024) {
        g_perm[i] = (int)(key[i] & 2047u);
        g_lenS[i] = 200 - (int)(key[i] >> 11);
    }
    __syncthreads();
    if (tid < Tlen) {
        const unsigned thr = (unsigned)(200 - tid) << 11;
        int lo = 0, hi = Bsz;
        while (lo < hi) {
            const int mid = (lo + hi) >> 1;
            if (key[mid] < thr) lo = mid + 1; else hi = mid;
        }
        const int cb = (lo + 127) >> 7;            // ceil(R/128)
        int nb = 4;
        while (nb < cb) nb <<= 1;                  // pow2ceil, min 4
        if (nb > 16) nb = 16;
        g_nbArr[tid] = nb;
        snb[tid] = nb;
    }
    __syncthreads();
    if (tid < Tlen) {
        int acc = 0;
        for (int tt = 0; tt <= tid; tt++) acc += 128 / snb[tt];
        g_tgt[tid]   = acc;
        g_trans[tid] = (tid > 0 && snb[tid] != snb[tid - 1]) ? 1 : 0;
    }
}

// ---------------------------------------------------------------------------
// Prolog 2: split x into packed bf16x2 hi/lo, permuted into sorted row order.
// ---------------------------------------------------------------------------
__global__ void split_x_kernel(const float* __restrict__ x)
{
    const int n2 = Bsz * (XSTR / 2);   // uint2 elements per dest
    for (int i = blockIdx.x * blockDim.x + threadIdx.x; i < n2;
         i += gridDim.x * blockDim.x) {
        const int srow = i / (XSTR / 2);
        const int rem  = i % (XSTR / 2);
        const int orow = g_perm[srow];
        float4 v = ((const float4*)x)[(size_t)orow * (XSTR / 2) + rem];
        uint2 wh, wl;
        wh.x = packbf(v.x, v.y);
        wh.y = packbf(v.z, v.w);
        wl.x = packbf(v.x - bfr(v.x), v.y - bfr(v.y));
        wl.y = packbf(v.z - bfr(v.z), v.w - bfr(v.w));
        ((uint2*)g_xh)[i] = wh;
        ((uint2*)g_xl)[i] = wl;
    }
}

// ---------------------------------------------------------------------------
// Prolog 3: weight reorder into fragment order + bf16 hi/lo split.
// ---------------------------------------------------------------------------
__global__ void reorder_frag(const float* __restrict__ W,
                             const float* __restrict__ bias,
                             int NC, int which)
{
    uint32_t* Wf = which ? g_W2f : g_W1f;
    float*    bd = which ? g_b2r : g_b1r;
    const int n = 32 * NC * 1024;
    for (int idx = blockIdx.x * blockDim.x + threadIdx.x; idx < n;
         idx += gridDim.x * blockDim.x) {
        int nt   = idx & 3;
        int lane = (idx >> 2) & 31;
        int r    = (idx >> 7) & 1;
        int ks2  = (idx >> 8) & 1;
        int hl   = (idx >> 9) & 1;
        int sc   = idx >> 10;
        int c    = sc % NC;
        int s    = sc / NC;

        int k0  = c * 32 + ks2 * 16 + r * 8 + 2 * (lane & 3);
        int col = s * 32 + nt * 8 + (lane >> 2);
        int h = col >> 2, g = col & 3;
        float w0 = W[k0 * G4H + g * Hdim + h];
        float w1 = W[(k0 + 1) * G4H + g * Hdim + h];
        Wf[idx] = (hl == 0)
            ? packbf(w0, w1)
            : packbf(w0 - bfr(w0), w1 - bfr(w1));

        if (idx < G4H) {
            int hh = idx >> 2, gg = idx & 3;
            bd[idx] = bias[gg * Hdim + hh];
        }
    }
}

__global__ void zero_kernel()
{
    const int idx = blockIdx.x * blockDim.x + threadIdx.x;
    if (idx == 0) g_bar = 0u;
    if (idx < 16) g_ctr[idx] = 0u;
    if (idx < Bsz * Hdim) {
        g_c1[idx] = 0.f; g_c2[idx] = 0.f; g_sum[idx] = 0.f;
    }
    if (idx < Bsz * HW) {
        g_h1h[0][idx] = 0u; g_h1l[0][idx] = 0u;
        g_h2h[0][idx] = 0u; g_h2l[0][idx] = 0u;
        g_h1h[1][idx] = 0u; g_h1l[1][idx] = 0u;
        g_h2h[1][idx] = 0u; g_h2l[1][idx] = 0u;
    }
}

// ---------------------------------------------------------------------------
// One layer phase, templated on LAYER and NB (active row blocks: 16/8/4).
// 2-stage cp.async double buffer (the R10/R11 proven pipeline), ldmatrix A
// fragments (single change vs R11), bf16 m16n8k16 3-term split GEMM, fused
// LSTM cell epilogue. c/sum state in gmem (.cg). Masked rows write nothing.
// ---------------------------------------------------------------------------
#define ASTR   20
#define A_LO_W 2560
#define B_W    5120
#define STGW   9216
#define STGB   (STGW * 4)          // 36864 B per stage
#define SMEM_TOTAL (2 * STGB)      // 73728 B
#define ZSTR   132

template <int LAYER, int NB>
__device__ __forceinline__ void phase_fn(int t)
{
    constexpr int NC   = (LAYER == 1) ? NC1 : NC2;
    constexpr int W0C  = (LAYER == 1) ? 4 : 8;   // chunks from segment 0
    constexpr int NT   = NB / 4;     // n8 tiles per warp
    constexpr int STRN = NB / 4;     // 32-col weight strips per CTA
    constexpr int WPS  = 4 / NT;     // warps sharing one strip
    constexpr int STRIPS = 128 / NB; // CTAs per row block
    constexpr int UPT  = NB / 2;     // units per epilogue thread

    extern __shared__ uint32_t smw[];
    uint32_t smb;
    asm("{ .reg .u64 t0; cvta.to.shared.u64 t0, %1; cvt.u32.u64 %0, t0; }"
        : "=r"(smb) : "l"(smw));

    const uint32_t* __restrict__ Wf = (LAYER == 1) ? g_W1f : g_W2f;
    const float*    __restrict__ bd = (LAYER == 1) ? g_b1r : g_b2r;
    float* __restrict__ cst = (LAYER == 1) ? g_c1 : g_c2;

    const int tid  = threadIdx.x;
    const int lane = tid & 31;
    const int gq   = lane >> 2;
    const int rq   = lane & 3;
    const int wid  = tid >> 5;
    const int wr   = wid & 3;
    const int wcol = wid >> 2;
    const int rb   = blockIdx.x / STRIPS;
    const int cs   = blockIdx.x % STRIPS;
    const int row0 = rb * 128;
    const int col0 = cs * (8 * NB);
    const int sbase = cs * STRN;
    const int prow = tid >> 2;
    const int pq   = tid & 3;
    const int erow = tid >> 2;
    const int eub  = (tid & 3) * UPT;

    const int p = t & 1;
    const uint32_t* s0h; const uint32_t* s0l; size_t s0s, s0k;
    if (LAYER == 1) { s0h = g_xh; s0l = g_xl; s0s = XSTR; s0k = (size_t)t * XW; }
    else            { s0h = g_h1h[p ^ 1]; s0l = g_h1l[p ^ 1]; s0s = HW; s0k = 0; }
    const uint32_t* hph = (LAYER == 1) ? g_h1h[p] : g_h2h[p];
    const uint32_t* hpl = (LAYER == 1) ? g_h1l[p] : g_h2l[p];
    uint32_t* hnh = (LAYER == 1) ? g_h1h[p ^ 1] : g_h2h[p ^ 1];
    uint32_t* hnl = (LAYER == 1) ? g_h1l[p ^ 1] : g_h2l[p ^ 1];

    // ---- epilogue ownership + state prefetch (hidden under GEMM) ----
    const int rowg  = row0 + erow;
    const int mylen = g_lenS[rowg];
    const bool valid = (t < mylen);
    const int gu0 = (col0 >> 2) + eub;
    float creg[UPT], sumr[UPT];
    if (valid) {
#pragma unroll
        for (int u = 0; u < UPT; u++) {
            creg[u] = __ldcg(&cst[rowg * Hdim + gu0 + u]);
            if (LAYER == 2) sumr[u] = __ldcg(&g_sum[rowg * Hdim + gu0 + u]);
        }
    }

    // ldmatrix lane address bases (per mt): row = wr*32 + mt*16 + (lane&15),
    // column halves selected by (lane>>4)*16 bytes. Row stride 80 B keeps
    // everything 16 B aligned; ks2 adds 32 B (k16..31 of the chunk).
    uint32_t a_addr[2];
#pragma unroll
    for (int mt = 0; mt < 2; mt++)
        a_addr[mt] = smb
            + (uint32_t)((wr * 32 + mt * 16 + (lane & 15)) * ASTR * 4)
            + (uint32_t)((lane >> 4) * 16);

    auto fill = [&](int c) {
        const uint32_t sb = smb + (uint32_t)(c & 1) * STGB;
        size_t off; const uint32_t *ph, *pl;
        if (c < W0C) {
            ph = s0h; pl = s0l;
            off = (size_t)(row0 + prow) * s0s + s0k + c * 16 + pq * 4;
        } else {
            ph = hph; pl = hpl;
            off = (size_t)(row0 + prow) * HW + (c - W0C) * 16 + pq * 4;
        }
        const uint32_t adst = sb + (uint32_t)(prow * ASTR + pq * 4) * 4u;
        CPASYNC16CG(adst, ph + off);                 // .cg: no stale L1
        CPASYNC16CG(adst + A_LO_W * 4u, pl + off);
        // B: STRN strips * 1024 words; 16B per op
#pragma unroll
        for (int o = 0; o < (STRN * 256 + 511) / 512; o++) {
            const int oo = tid + o * 512;
            if ((STRN * 256 % 512 == 0) || (oo < STRN * 256)) {
                const int j = oo >> 8;
                const int w = (oo & 255) * 4;
                const uint32_t* src =
                    Wf + ((size_t)(sbase + j) * NC + c) * 1024 + w;
                CPASYNC16(sb + (uint32_t)(B_W + j * 1024 + w) * 4u, src);
            }
        }
    };

    float acc[2][NT][4];
#pragma unroll
    for (int mt = 0; mt < 2; mt++)
#pragma unroll
        for (int nt = 0; nt < NT; nt++)
#pragma unroll
            for (int q = 0; q < 4; q++) acc[mt][nt][q] = 0.0f;

    fill(0);
    CP_COMMIT();

#pragma unroll 1
    for (int c = 0; c < NC; c++) {
        CP_WAIT0();            // chunk c landed
        __syncthreads();       // data published + prior compute done
        if (c + 1 < NC) { fill(c + 1); CP_COMMIT(); }

        const uint32_t soff = (uint32_t)(c & 1) * STGB;
        const uint32_t* bb  = smw + (c & 1) * STGW + B_W
                            + (wcol / WPS) * 1024 + (wcol % WPS) * NT;

#pragma unroll
        for (int ks2 = 0; ks2 < 2; ks2++) {
            uint32_t bh0[NT], bh1[NT], bl0[NT], bl1[NT];
            if (NT == 4) {
                *(uint4*)bh0 = *(const uint4*)(bb + ks2 * 256 + lane * 4);
                *(uint4*)bh1 = *(const uint4*)(bb + ks2 * 256 + 128 + lane * 4);
                *(uint4*)bl0 = *(const uint4*)(bb + 512 + ks2 * 256 + lane * 4);
                *(uint4*)bl1 = *(const uint4*)(bb + 512 + ks2 * 256 + 128 + lane * 4);
            } else if (NT == 2) {
                *(uint2*)bh0 = *(const uint2*)(bb + ks2 * 256 + lane * 4);
                *(uint2*)bh1 = *(const uint2*)(bb + ks2 * 256 + 128 + lane * 4);
                *(uint2*)bl0 = *(const uint2*)(bb + 512 + ks2 * 256 + lane * 4);
                *(uint2*)bl1 = *(const uint2*)(bb + 512 + ks2 * 256 + 128 + lane * 4);
            } else {
                bh0[0] = bb[ks2 * 256 + lane * 4];
                bh1[0] = bb[ks2 * 256 + 128 + lane * 4];
                bl0[0] = bb[512 + ks2 * 256 + lane * 4];
                bl1[0] = bb[512 + ks2 * 256 + 128 + lane * 4];
            }

#pragma unroll
            for (int mt = 0; mt < 2; mt++) {
                uint32_t ah[4], al[4];
                const uint32_t ab = a_addr[mt] + soff + (uint32_t)(ks2 * 32);
                LDSM_X4(ah[0], ah[1], ah[2], ah[3], ab);
                LDSM_X4(al[0], al[1], al[2], al[3], ab + A_LO_W * 4u);
#pragma unroll
                for (int nt = 0; nt < NT; nt++) {
                    uint32_t bhp[2] = { bh0[nt], bh1[nt] };
                    uint32_t blp[2] = { bl0[nt], bl1[nt] };
                    mma_bf16(acc[mt][nt], ah, bhp);
                    mma_bf16(acc[mt][nt], ah, blp);
                    mma_bf16(acc[mt][nt], al, bhp);
                }
            }
        }
    }
    __syncthreads();   // all compute done before Z overwrites stages

    // ---- stage Z in smem ----
    float* Zs = (float*)smw;
#pragma unroll
    for (int mt = 0; mt < 2; mt++)
#pragma unroll
        for (int nt = 0; nt < NT; nt++) {
            const int row = wr * 32 + mt * 16 + gq;
            const int col = wcol * (8 * NT) + nt * 8 + 2 * rq;
            Zs[row * ZSTR + col]           = acc[mt][nt][0];
            Zs[row * ZSTR + col + 1]       = acc[mt][nt][1];
            Zs[(row + 8) * ZSTR + col]     = acc[mt][nt][2];
            Zs[(row + 8) * ZSTR + col + 1] = acc[mt][nt][3];
        }
    __syncthreads();

    // ---- fused LSTM cell (valid rows only) ----
    if (valid) {
        const size_t hw0 = (size_t)rowg * HW + (gu0 >> 1);
#pragma unroll
        for (int u2 = 0; u2 < UPT / 2; u2++) {
            float nhv[2];
#pragma unroll
            for (int e = 0; e < 2; e++) {
                const int uu = 2 * u2 + e;
                const int n4 = (eub + uu) * 4;
                float4 z  = *(const float4*)&Zs[erow * ZSTR + n4];
                float4 bv = *(const float4*)&bd[col0 + n4];
                const float zi = z.x + bv.x;
                const float zj = z.y + bv.y;
                const float zf = z.z + bv.z;
                const float zo = z.w + bv.w;
                const float nc = creg[uu] * fast_sig(zf + 1.0f)
                               + fast_sig(zi) * fast_tanh(zj);
                const float nh = fast_tanh(nc) * fast_sig(zo);
                creg[uu] = nc;
                if (LAYER == 2) sumr[uu] += nh;
                nhv[e] = nh;
            }
            hnh[hw0 + u2] = packbf(nhv[0], nhv[1]);
            hnl[hw0 + u2] = packbf(nhv[0] - bfr(nhv[0]),
                                   nhv[1] - bfr(nhv[1]));
        }
#pragma unroll
        for (int u = 0; u < UPT; u++) {
            __stcg(&cst[rowg * Hdim + gu0 + u], creg[u]);
            if (LAYER == 2) __stcg(&g_sum[rowg * Hdim + gu0 + u], sumr[u]);
        }
    }
    __syncthreads();   // Z reads done before next phase's fill
}

// ---------------------------------------------------------------------------
// Persistent kernel: 128 CTAs, 200 steps x 2 layers.
// Per-step LOCAL row-block barrier (128/nb CTAs); GLOBAL barrier only at
// nb transitions (<=2 per run), where the CTA<->block mapping changes.
// ---------------------------------------------------------------------------
__global__ void __launch_bounds__(512, 1)
lstm_persist()
{
    const int tid = threadIdx.x;
    int ntrans = 0;

#pragma unroll 1
    for (int t = 0; t < Tlen; t++) {
        const int nb = g_nbArr[t];

        // Global barrier at nb transitions: CTA->row-block mapping changes,
        // so the previous step's writers are a different CTA set.
        if (t > 0 && g_trans[t]) {
            ntrans++;
            if (tid == 0) {
                unsigned* bp = &g_bar;
                asm volatile("red.release.gpu.add.u32 [%0], 1;" :: "l"(bp) : "memory");
                const unsigned tgt = 128u * (unsigned)ntrans;
                unsigned v;
                while (true) {
                    asm volatile("ld.acquire.gpu.b32 %0, [%1];"
                                 : "=r"(v) : "l"(bp) : "memory");
                    if (v >= tgt) break;
                    asm volatile("nanosleep.u32 128;");
                }
            }
            __syncthreads();
        }

        if (nb == 16)     phase_fn<1, 16>(t);
        else if (nb == 8) phase_fn<1, 8>(t);
        else              phase_fn<1, 4>(t);

        // Local row-block barrier (128/nb CTAs), cumulative target g_tgt[t].
        {
            const int strips = 128 / nb;
            if (tid == 0) {
                unsigned* bp = &g_ctr[blockIdx.x / strips];
                asm volatile("red.release.gpu.add.u32 [%0], 1;" :: "l"(bp) : "memory");
                const unsigned tgt = (unsigned)g_tgt[t];
                unsigned v;
                while (true) {
                    asm volatile("ld.acquire.gpu.b32 %0, [%1];"
                                 : "=r"(v) : "l"(bp) : "memory");
                    if (v >= tgt) break;
                    asm volatile("nanosleep.u32 64;");
                }
            }
            __syncthreads();
        }

        if (nb == 16)     phase_fn<2, 16>(t);
        else if (nb == 8) phase_fn<2, 8>(t);
        else              phase_fn<2, 4>(t);
    }
}

// ---------------------------------------------------------------------------
// logits[orig b, o] = dot(sum_sorted[srow,:], Wout[:,o]) / lenS[srow] + bout[o]
// ---------------------------------------------------------------------------
__global__ void final_kernel(const float* __restrict__ Wout,
                             const float* __restrict__ bout,
                             float* __restrict__ out)
{
    const int idx = blockIdx.x * blockDim.x + threadIdx.x;
    if (idx >= Bsz * Odim) return;
    const int srow = idx / Odim;
    const int o    = idx % Odim;
    const float* s = g_sum + srow * Hdim;
    float acc = 0.0f;
#pragma unroll 8
    for (int h = 0; h < Hdim; h++) acc += s[h] * Wout[h * Odim + o];
    out[g_perm[srow] * Odim + o] =
        acc / (float)g_lenS[srow] + bout[o];
}

// ---------------------------------------------------------------------------
// Inputs (metadata order): x, lengths, W1, b1, W2, b2, Wout, bout
// ---------------------------------------------------------------------------
extern "C" void kernel_launch(void* const* d_in, const int* in_sizes, int n_in,
                              void* d_out, int out_size)
{
    const float* x       = (const float*)d_in[0];
    const int*   lengths = (const int*)d_in[1];
    const float* W1      = (const float*)d_in[2];
    const float* b1      = (const float*)d_in[3];
    const float* W2      = (const float*)d_in[4];
    const float* b2      = (const float*)d_in[5];
    const float* Wout    = (const float*)d_in[6];
    const float* bout    = (const float*)d_in[7];
    float* out = (float*)d_out;

    cudaFuncSetAttribute(lstm_persist,
                         cudaFuncAttributeMaxDynamicSharedMemorySize, SMEM_TOTAL);

    sort_kernel<<<1, 1024>>>(lengths);
    split_x_kernel<<<4096, 256>>>(x);
    reorder_frag<<<1536, 256>>>(W1, b1, NC1, 0);
    reorder_frag<<<2048, 256>>>(W2, b2, NC2, 1);
    zero_kernel<<<2048, 256>>>();

    lstm_persist<<<128, 512, SMEM_TOTAL>>>();

    final_kernel<<<(Bsz * Odim + 255) / 256, 256>>>(Wout, bout, out);
}

// round 16
// speedup vs baseline: 1.0764x; 1.0520x over previous
#include <cuda_runtime.h>
#include <cuda_bf16.h>
#include <math.h>
#include <stdint.h>

// Problem constants
#define Bsz  2048
#define Tlen 200
#define Fdim 128
#define Hdim 256
#define Odim 6
#define G4H  1024
#define NC1_32 12        // 384/32  (weight gmem layout granularity)
#define NC2_32 16        // 512/32
#define HW   (Hdim / 2)  // packed bf16x2 words per h row  (128)
#define XW   (Fdim / 2)  // packed words per x row          (64)
#define XSTR (Tlen * XW) // x packed row stride per batch

// ---------------------------------------------------------------------------
// Persistent device scratch. ALL batch-indexed arrays use SORTED row order
// (rows sorted by length descending; perm maps sorted -> original).
// ---------------------------------------------------------------------------
__device__ uint32_t g_h1h[2][Bsz * HW];
__device__ uint32_t g_h1l[2][Bsz * HW];
__device__ uint32_t g_h2h[2][Bsz * HW];
__device__ uint32_t g_h2l[2][Bsz * HW];
__device__ float    g_c1[Bsz * Hdim];
__device__ float    g_c2[Bsz * Hdim];
__device__ float    g_sum[Bsz * Hdim];
__device__ int      g_perm[Bsz];      // sorted row -> original row
__device__ int      g_lenS[Bsz];      // sorted lengths (descending)
__device__ int      g_nbArr[Tlen];    // active row-block count per step (16/8/4)
__device__ int      g_tgt[Tlen];      // cumulative per-block arrival target
__device__ int      g_trans[Tlen];    // 1 if nb changed vs previous step
__device__ unsigned g_ctr[16];        // per-row-block local barrier counters
__device__ unsigned g_bar;            // global barrier counter (transitions)

// Pre-split x (SORTED rows): packed bf16x2 words, layout [srow][t][f/2].
__device__ uint32_t g_xh[Bsz * Tlen * XW];
__device__ uint32_t g_xl[Bsz * Tlen * XW];

// Weights: gate-interleaved cols (h*4+g), bf16 hi/lo split, FRAGMENT-ordered:
// per (32-col strip s, 32-wide chunk c32): 1024 words = [hl][ks2][r][lane][nt]
// Consecutive c32 blocks are contiguous, so a 64-wide chunk is one 2048-word
// contiguous region.
__device__ uint32_t g_W1f[32 * NC1_32 * 1024];
__device__ uint32_t g_W2f[32 * NC2_32 * 1024];
__device__ float    g_b1r[G4H];
__device__ float    g_b2r[G4H];

// ---------------------------------------------------------------------------
// helpers
// ---------------------------------------------------------------------------
__device__ __forceinline__ float bfr(float a) {
    return __bfloat162float(__float2bfloat16(a));
}
__device__ __forceinline__ uint32_t packbf(float e0, float e1) {
    uint32_t d;
    asm("cvt.rn.bf16x2.f32 %0, %1, %2;" : "=r"(d) : "f"(e1), "f"(e0));
    return d;
}
__device__ __forceinline__ void mma_bf16(float* c, const uint32_t* a,
                                         const uint32_t* b) {
    asm volatile(
        "mma.sync.aligned.m16n8k16.row.col.f32.bf16.bf16.f32 "
        "{%0,%1,%2,%3}, {%4,%5,%6,%7}, {%8,%9}, {%0,%1,%2,%3};"
        : "+f"(c[0]), "+f"(c[1]), "+f"(c[2]), "+f"(c[3])
        : "r"(a[0]), "r"(a[1]), "r"(a[2]), "r"(a[3]), "r"(b[0]), "r"(b[1]));
}

// ldmatrix x4: loads the full m16k16 A fragment (4 regs) in one op.
#define LDSM_X4(r0, r1, r2, r3, addr) \
    asm volatile("ldmatrix.sync.aligned.m8n8.x4.shared.b16 {%0,%1,%2,%3}, [%4];" \
        : "=r"(r0), "=r"(r1), "=r"(r2), "=r"(r3) : "r"(addr))

#define CPASYNC16(dst, src) \
    asm volatile("cp.async.ca.shared.global [%0], [%1], 16;" :: "r"(dst), "l"(src))
#define CPASYNC16CG(dst, src) \
    asm volatile("cp.async.cg.shared.global [%0], [%1], 16;" :: "r"(dst), "l"(src))
#define CP_COMMIT() asm volatile("cp.async.commit_group;")
#define CP_WAIT0()  asm volatile("cp.async.wait_group 0;")

__device__ __forceinline__ float fast_sig(float v)  { return 1.0f / (1.0f + __expf(-v)); }
__device__ __forceinline__ float fast_tanh(float v) { return 1.0f - 2.0f / (__expf(2.0f * v) + 1.0f); }

// ---------------------------------------------------------------------------
// Prolog 1: sort rows by length desc (bitonic, deterministic, idx asc ties),
// build perm/lenS, the per-step schedule nbArr, the cumulative local-barrier
// targets tgt[t] = sum_{t'<=t} 128/nb(t'), and transition flags.
// ---------------------------------------------------------------------------
__global__ void sort_kernel(const int* __restrict__ lengths)
{
    __shared__ unsigned key[Bsz];
    __shared__ int snb[Tlen];
    const int tid = threadIdx.x;       // 1024 threads
    key[tid]        = ((unsigned)(200 - lengths[tid]) << 11) | (unsigned)tid;
    key[tid + 1024] = ((unsigned)(200 - lengths[tid + 1024]) << 11)
                      | (unsigned)(tid + 1024);
    __syncthreads();
    for (int k = 2; k <= Bsz; k <<= 1) {
        for (int j = k >> 1; j > 0; j >>= 1) {
            const int i   = ((tid & ~(j - 1)) << 1) | (tid & (j - 1));
            const int par = i | j;
            const bool up = ((i & k) == 0);
            const unsigned a = key[i], b = key[par];
            if (up ? (a > b) : (a < b)) { key[i] = b; key[par] = a; }
            __syncthreads();
        }
    }
    for (int i = tid; i < Bsz; i += 1024) {
        g_perm[i] = (int)(key[i] & 2047u);
        g_lenS[i] = 200 - (int)(key[i] >> 11);
    }
    __syncthreads();
    if (tid < Tlen) {
        const unsigned thr = (unsigned)(200 - tid) << 11;
        int lo = 0, hi = Bsz;
        while (lo < hi) {
            const int mid = (lo + hi) >> 1;
            if (key[mid] < thr) lo = mid + 1; else hi = mid;
        }
        const int cb = (lo + 127) >> 7;            // ceil(R/128)
        int nb = 4;
        while (nb < cb) nb <<= 1;                  // pow2ceil, min 4
        if (nb > 16) nb = 16;
        g_nbArr[tid] = nb;
        snb[tid] = nb;
    }
    __syncthreads();
    if (tid < Tlen) {
        int acc = 0;
        for (int tt = 0; tt <= tid; tt++) acc += 128 / snb[tt];
        g_tgt[tid]   = acc;
        g_trans[tid] = (tid > 0 && snb[tid] != snb[tid - 1]) ? 1 : 0;
    }
}

// ---------------------------------------------------------------------------
// Prolog 2: split x into packed bf16x2 hi/lo, permuted into sorted row order.
// ---------------------------------------------------------------------------
__global__ void split_x_kernel(const float* __restrict__ x)
{
    const int n2 = Bsz * (XSTR / 2);   // uint2 elements per dest
    for (int i = blockIdx.x * blockDim.x + threadIdx.x; i < n2;
         i += gridDim.x * blockDim.x) {
        const int srow = i / (XSTR / 2);
        const int rem  = i % (XSTR / 2);
        const int orow = g_perm[srow];
        float4 v = ((const float4*)x)[(size_t)orow * (XSTR / 2) + rem];
        uint2 wh, wl;
        wh.x = packbf(v.x, v.y);
        wh.y = packbf(v.z, v.w);
        wl.x = packbf(v.x - bfr(v.x), v.y - bfr(v.y));
        wl.y = packbf(v.z - bfr(v.z), v.w - bfr(v.w));
        ((uint2*)g_xh)[i] = wh;
        ((uint2*)g_xl)[i] = wl;
    }
}

// ---------------------------------------------------------------------------
// Prolog 3: weight reorder into fragment order + bf16 hi/lo split.
// ---------------------------------------------------------------------------
__global__ void reorder_frag(const float* __restrict__ W,
                             const float* __restrict__ bias,
                             int NC, int which)
{
    uint32_t* Wf = which ? g_W2f : g_W1f;
    float*    bd = which ? g_b2r : g_b1r;
    const int n = 32 * NC * 1024;
    for (int idx = blockIdx.x * blockDim.x + threadIdx.x; idx < n;
         idx += gridDim.x * blockDim.x) {
        int nt   = idx & 3;
        int lane = (idx >> 2) & 31;
        int r    = (idx >> 7) & 1;
        int ks2  = (idx >> 8) & 1;
        int hl   = (idx >> 9) & 1;
        int sc   = idx >> 10;
        int c    = sc % NC;
        int s    = sc / NC;

        int k0  = c * 32 + ks2 * 16 + r * 8 + 2 * (lane & 3);
        int col = s * 32 + nt * 8 + (lane >> 2);
        int h = col >> 2, g = col & 3;
        float w0 = W[k0 * G4H + g * Hdim + h];
        float w1 = W[(k0 + 1) * G4H + g * Hdim + h];
        Wf[idx] = (hl == 0)
            ? packbf(w0, w1)
            : packbf(w0 - bfr(w0), w1 - bfr(w1));

        if (idx < G4H) {
            int hh = idx >> 2, gg = idx & 3;
            bd[idx] = bias[gg * Hdim + hh];
        }
    }
}

__global__ void zero_kernel()
{
    const int idx = blockIdx.x * blockDim.x + threadIdx.x;
    if (idx == 0) g_bar = 0u;
    if (idx < 16) g_ctr[idx] = 0u;
    if (idx < Bsz * Hdim) {
        g_c1[idx] = 0.f; g_c2[idx] = 0.f; g_sum[idx] = 0.f;
    }
    if (idx < Bsz * HW) {
        g_h1h[0][idx] = 0u; g_h1l[0][idx] = 0u;
        g_h2h[0][idx] = 0u; g_h2l[0][idx] = 0u;
        g_h1h[1][idx] = 0u; g_h1l[1][idx] = 0u;
        g_h2h[1][idx] = 0u; g_h2l[1][idx] = 0u;
    }
}

// ---------------------------------------------------------------------------
// One layer phase, templated on LAYER and NB (active row blocks: 16/8/4).
// KC=64 chunks (half the chunk boundaries of the KC=32 version; each compute
// phase now exceeds the cp.async fill latency so wait_group 0 rarely blocks),
// 2-stage double buffer (the proven-safe pipeline shape), ldmatrix A
// fragments, bf16 m16n8k16 3-term split GEMM in the SAME k-step order as the
// KC=32 kernel (numerically bit-identical), fused LSTM cell epilogue.
// c/sum state in gmem (.cg). Masked rows (past length) write nothing.
// ---------------------------------------------------------------------------
#define ASTR   36                  // 32 data words + 4 pad (144 B rows)
#define A_LO_W 4608                // 128 * 36
#define B_W    9216                // 2 * 4608
#define STGW   (B_W + 4 * 2048)    // 17408 words (B sized for STRN=4)
#define STGB   (STGW * 4)          // 69632 B per stage
#define SMEM_TOTAL (2 * STGB)      // 139264 B
#define ZSTR   132

template <int LAYER, int NB>
__device__ __forceinline__ void phase_fn(int t)
{
    constexpr int NC   = (LAYER == 1) ? 6 : 8;    // K/64
    constexpr int W0C  = (LAYER == 1) ? 2 : 4;    // 64-chunks from segment 0
    constexpr int NC32 = (LAYER == 1) ? NC1_32 : NC2_32;  // weight granularity
    constexpr int NT   = NB / 4;     // n8 tiles per warp
    constexpr int STRN = NB / 4;     // 32-col weight strips per CTA
    constexpr int WPS  = 4 / NT;     // warps sharing one strip
    constexpr int STRIPS = 128 / NB; // CTAs per row block
    constexpr int UPT  = NB / 2;     // units per epilogue thread

    extern __shared__ uint32_t smw[];
    uint32_t smb;
    asm("{ .reg .u64 t0; cvta.to.shared.u64 t0, %1; cvt.u32.u64 %0, t0; }"
        : "=r"(smb) : "l"(smw));

    const uint32_t* __restrict__ Wf = (LAYER == 1) ? g_W1f : g_W2f;
    const float*    __restrict__ bd = (LAYER == 1) ? g_b1r : g_b2r;
    float* __restrict__ cst = (LAYER == 1) ? g_c1 : g_c2;

    const int tid  = threadIdx.x;
    const int lane = tid & 31;
    const int gq   = lane >> 2;
    const int rq   = lane & 3;
    const int wid  = tid >> 5;
    const int wr   = wid & 3;
    const int wcol = wid >> 2;
    const int rb   = blockIdx.x / STRIPS;
    const int cs   = blockIdx.x % STRIPS;
    const int row0 = rb * 128;
    const int col0 = cs * (8 * NB);
    const int sbase = cs * STRN;
    const int prow = tid >> 2;
    const int pq   = tid & 3;
    const int erow = tid >> 2;
    const int eub  = (tid & 3) * UPT;

    const int p = t & 1;
    const uint32_t* s0h; const uint32_t* s0l; size_t s0s, s0k;
    if (LAYER == 1) { s0h = g_xh; s0l = g_xl; s0s = XSTR; s0k = (size_t)t * XW; }
    else            { s0h = g_h1h[p ^ 1]; s0l = g_h1l[p ^ 1]; s0s = HW; s0k = 0; }
    const uint32_t* hph = (LAYER == 1) ? g_h1h[p] : g_h2h[p];
    const uint32_t* hpl = (LAYER == 1) ? g_h1l[p] : g_h2l[p];
    uint32_t* hnh = (LAYER == 1) ? g_h1h[p ^ 1] : g_h2h[p ^ 1];
    uint32_t* hnl = (LAYER == 1) ? g_h1l[p ^ 1] : g_h2l[p ^ 1];

    // ---- epilogue ownership + state prefetch (hidden under GEMM) ----
    const int rowg  = row0 + erow;
    const int mylen = g_lenS[rowg];
    const bool valid = (t < mylen);
    const int gu0 = (col0 >> 2) + eub;
    float creg[UPT], sumr[UPT];
    if (valid) {
#pragma unroll
        for (int u = 0; u < UPT; u++) {
            creg[u] = __ldcg(&cst[rowg * Hdim + gu0 + u]);
            if (LAYER == 2) sumr[u] = __ldcg(&g_sum[rowg * Hdim + gu0 + u]);
        }
    }

    // ldmatrix lane address bases (per mt): row = wr*32 + mt*16 + (lane&15),
    // k-halves selected by (lane>>4)*16 bytes; ks adds 32 B per k16 substep.
    // Row stride 144 B keeps the 8 row addresses in distinct 16 B slots.
    uint32_t a_addr[2];
#pragma unroll
    for (int mt = 0; mt < 2; mt++)
        a_addr[mt] = smb
            + (uint32_t)((wr * 32 + mt * 16 + (lane & 15)) * ASTR * 4)
            + (uint32_t)((lane >> 4) * 16);

    auto fill = [&](int c) {
        const uint32_t sb = smb + (uint32_t)(c & 1) * STGB;
        size_t off; const uint32_t *ph, *pl;
        if (c < W0C) {
            ph = s0h; pl = s0l;
            off = (size_t)(row0 + prow) * s0s + s0k + c * 32 + pq * 8;
        } else {
            ph = hph; pl = hpl;
            off = (size_t)(row0 + prow) * HW + (c - W0C) * 32 + pq * 8;
        }
        // A: 2 x 16B hi + 2 x 16B lo per thread (row = 32 words = 8 quads)
        const uint32_t adst = sb + (uint32_t)(prow * ASTR + pq * 8) * 4u;
        CPASYNC16CG(adst, ph + off);                 // .cg: no stale L1
        CPASYNC16CG(adst + 16u, ph + off + 4);
        CPASYNC16CG(adst + A_LO_W * 4u, pl + off);
        CPASYNC16CG(adst + A_LO_W * 4u + 16u, pl + off + 4);
        // B: STRN strips x 2048 words (two contiguous c32 blocks per strip)
#pragma unroll
        for (int o = 0; o < STRN; o++) {
            const int oo = tid + o * 512;            // [0, STRN*512)
            const int j = oo >> 9;                   // strip
            const int w = (oo & 511) * 4;            // word within 2048
            const uint32_t* src =
                Wf + ((size_t)(sbase + j) * NC32 + 2 * c) * 1024 + w;
            CPASYNC16(sb + (uint32_t)(B_W + j * 2048 + w) * 4u, src);
        }
    };

    float acc[2][NT][4];
#pragma unroll
    for (int mt = 0; mt < 2; mt++)
#pragma unroll
        for (int nt = 0; nt < NT; nt++)
#pragma unroll
            for (int q = 0; q < 4; q++) acc[mt][nt][q] = 0.0f;

    fill(0);
    CP_COMMIT();

#pragma unroll 1
    for (int c = 0; c < NC; c++) {
        CP_WAIT0();            // chunk c landed
        __syncthreads();       // data published + prior compute done
        if (c + 1 < NC) { fill(c + 1); CP_COMMIT(); }

        const uint32_t soff = (uint32_t)(c & 1) * STGB;
        const uint32_t* bb  = smw + (c & 1) * STGW + B_W
                            + (wcol / WPS) * 2048 + (wcol % WPS) * NT;

#pragma unroll
        for (int ks = 0; ks < 4; ks++) {
            const int kb = (ks >> 1) * 1024 + (ks & 1) * 256;
            uint32_t bh0[NT], bh1[NT], bl0[NT], bl1[NT];
            if (NT == 4) {
                *(uint4*)bh0 = *(const uint4*)(bb + kb + lane * 4);
                *(uint4*)bh1 = *(const uint4*)(bb + kb + 128 + lane * 4);
                *(uint4*)bl0 = *(const uint4*)(bb + kb + 512 + lane * 4);
                *(uint4*)bl1 = *(const uint4*)(bb + kb + 512 + 128 + lane * 4);
            } else if (NT == 2) {
                *(uint2*)bh0 = *(const uint2*)(bb + kb + lane * 4);
                *(uint2*)bh1 = *(const uint2*)(bb + kb + 128 + lane * 4);
                *(uint2*)bl0 = *(const uint2*)(bb + kb + 512 + lane * 4);
                *(uint2*)bl1 = *(const uint2*)(bb + kb + 512 + 128 + lane * 4);
            } else {
                bh0[0] = bb[kb + lane * 4];
                bh1[0] = bb[kb + 128 + lane * 4];
                bl0[0] = bb[kb + 512 + lane * 4];
                bl1[0] = bb[kb + 512 + 128 + lane * 4];
            }

#pragma unroll
            for (int mt = 0; mt < 2; mt++) {
                uint32_t ah[4], al[4];
                const uint32_t ab = a_addr[mt] + soff + (uint32_t)(ks * 32);
                LDSM_X4(ah[0], ah[1], ah[2], ah[3], ab);
                LDSM_X4(al[0], al[1], al[2], al[3], ab + A_LO_W * 4u);
#pragma unroll
                for (int nt = 0; nt < NT; nt++) {
                    uint32_t bhp[2] = { bh0[nt], bh1[nt] };
                    uint32_t blp[2] = { bl0[nt], bl1[nt] };
                    mma_bf16(acc[mt][nt], ah, bhp);
                    mma_bf16(acc[mt][nt], ah, blp);
                    mma_bf16(acc[mt][nt], al, bhp);
                }
            }
        }
    }
    __syncthreads();   // all compute done before Z overwrites stages

    // ---- stage Z in smem ----
    float* Zs = (float*)smw;
#pragma unroll
    for (int mt = 0; mt < 2; mt++)
#pragma unroll
        for (int nt = 0; nt < NT; nt++) {
            const int row = wr * 32 + mt * 16 + gq;
            const int col = wcol * (8 * NT) + nt * 8 + 2 * rq;
            Zs[row * ZSTR + col]           = acc[mt][nt][0];
            Zs[row * ZSTR + col + 1]       = acc[mt][nt][1];
            Zs[(row + 8) * ZSTR + col]     = acc[mt][nt][2];
            Zs[(row + 8) * ZSTR + col + 1] = acc[mt][nt][3];
        }
    __syncthreads();

    // ---- fused LSTM cell (valid rows only) ----
    if (valid) {
        const size_t hw0 = (size_t)rowg * HW + (gu0 >> 1);
#pragma unroll
        for (int u2 = 0; u2 < UPT / 2; u2++) {
            float nhv[2];
#pragma unroll
            for (int e = 0; e < 2; e++) {
                const int uu = 2 * u2 + e;
                const int n4 = (eub + uu) * 4;
                float4 z  = *(const float4*)&Zs[erow * ZSTR + n4];
                float4 bv = *(const float4*)&bd[col0 + n4];
                const float zi = z.x + bv.x;
                const float zj = z.y + bv.y;
                const float zf = z.z + bv.z;
                const float zo = z.w + bv.w;
                const float nc = creg[uu] * fast_sig(zf + 1.0f)
                               + fast_sig(zi) * fast_tanh(zj);
                const float nh = fast_tanh(nc) * fast_sig(zo);
                creg[uu] = nc;
                if (LAYER == 2) sumr[uu] += nh;
                nhv[e] = nh;
            }
            hnh[hw0 + u2] = packbf(nhv[0], nhv[1]);
            hnl[hw0 + u2] = packbf(nhv[0] - bfr(nhv[0]),
                                   nhv[1] - bfr(nhv[1]));
        }
#pragma unroll
        for (int u = 0; u < UPT; u++) {
            __stcg(&cst[rowg * Hdim + gu0 + u], creg[u]);
            if (LAYER == 2) __stcg(&g_sum[rowg * Hdim + gu0 + u], sumr[u]);
        }
    }
    __syncthreads();   // Z reads done before next phase's fill
}

// ---------------------------------------------------------------------------
// Persistent kernel: 128 CTAs, 200 steps x 2 layers.
// Per-step LOCAL row-block barrier (128/nb CTAs); GLOBAL barrier only at
// nb transitions (<=2 per run), where the CTA<->block mapping changes.
// ---------------------------------------------------------------------------
__global__ void __launch_bounds__(512, 1)
lstm_persist()
{
    const int tid = threadIdx.x;
    int ntrans = 0;

#pragma unroll 1
    for (int t = 0; t < Tlen; t++) {
        const int nb = g_nbArr[t];

        // Global barrier at nb transitions: CTA->row-block mapping changes,
        // so the previous step's writers are a different CTA set.
        if (t > 0 && g_trans[t]) {
            ntrans++;
            if (tid == 0) {
                unsigned* bp = &g_bar;
                asm volatile("red.release.gpu.add.u32 [%0], 1;" :: "l"(bp) : "memory");
                const unsigned tgt = 128u * (unsigned)ntrans;
                unsigned v;
                while (true) {
                    asm volatile("ld.acquire.gpu.b32 %0, [%1];"
                                 : "=r"(v) : "l"(bp) : "memory");
                    if (v >= tgt) break;
                    asm volatile("nanosleep.u32 128;");
                }
            }
            __syncthreads();
        }

        if (nb == 16)     phase_fn<1, 16>(t);
        else if (nb == 8) phase_fn<1, 8>(t);
        else              phase_fn<1, 4>(t);

        // Local row-block barrier (128/nb CTAs), cumulative target g_tgt[t].
        {
            const int strips = 128 / nb;
            if (tid == 0) {
                unsigned* bp = &g_ctr[blockIdx.x / strips];
                asm volatile("red.release.gpu.add.u32 [%0], 1;" :: "l"(bp) : "memory");
                const unsigned tgt = (unsigned)g_tgt[t];
                unsigned v;
                while (true) {
                    asm volatile("ld.acquire.gpu.b32 %0, [%1];"
                                 : "=r"(v) : "l"(bp) : "memory");
                    if (v >= tgt) break;
                    asm volatile("nanosleep.u32 64;");
                }
            }
            __syncthreads();
        }

        if (nb == 16)     phase_fn<2, 16>(t);
        else if (nb == 8) phase_fn<2, 8>(t);
        else              phase_fn<2, 4>(t);
    }
}

// ---------------------------------------------------------------------------
// logits[orig b, o] = dot(sum_sorted[srow,:], Wout[:,o]) / lenS[srow] + bout[o]
// ---------------------------------------------------------------------------
__global__ void final_kernel(const float* __restrict__ Wout,
                             const float* __restrict__ bout,
                             float* __restrict__ out)
{
    const int idx = blockIdx.x * blockDim.x + threadIdx.x;
    if (idx >= Bsz * Odim) return;
    const int srow = idx / Odim;
    const int o    = idx % Odim;
    const float* s = g_sum + srow * Hdim;
    float acc = 0.0f;
#pragma unroll 8
    for (int h = 0; h < Hdim; h++) acc += s[h] * Wout[h * Odim + o];
    out[g_perm[srow] * Odim + o] =
        acc / (float)g_lenS[srow] + bout[o];
}

// ---------------------------------------------------------------------------
// Inputs (metadata order): x, lengths, W1, b1, W2, b2, Wout, bout
// ---------------------------------------------------------------------------
extern "C" void kernel_launch(void* const* d_in, const int* in_sizes, int n_in,
                              void* d_out, int out_size)
{
    const float* x       = (const float*)d_in[0];
    const int*   lengths = (const int*)d_in[1];
    const float* W1      = (const float*)d_in[2];
    const float* b1      = (const float*)d_in[3];
    const float* W2      = (const float*)d_in[4];
    const float* b2      = (const float*)d_in[5];
    const float* Wout    = (const float*)d_in[6];
    const float* bout    = (const float*)d_in[7];
    float* out = (float*)d_out;

    cudaFuncSetAttribute(lstm_persist,
                         cudaFuncAttributeMaxDynamicSharedMemorySize, SMEM_TOTAL);

    sort_kernel<<<1, 1024>>>(lengths);
    split_x_kernel<<<4096, 256>>>(x);
    reorder_frag<<<1536, 256>>>(W1, b1, NC1_32, 0);
    reorder_frag<<<2048, 256>>>(W2, b2, NC2_32, 1);
    zero_kernel<<<2048, 256>>>();

    lstm_persist<<<128, 512, SMEM_TOTAL>>>();

    final_kernel<<<(Bsz * Odim + 255) / 256, 256>>>(Wout, bout, out);
}

// round 17
// speedup vs baseline: 1.0775x; 1.0011x over previous
#include <cuda_runtime.h>
#include <cuda_bf16.h>
#include <math.h>
#include <stdint.h>

// Problem constants
#define Bsz  2048
#define Tlen 200
#define Fdim 128
#define Hdim 256
#define Odim 6
#define G4H  1024
#define NC1_32 12        // 384/32  (weight gmem layout granularity)
#define NC2_32 16        // 512/32
#define HW   (Hdim / 2)  // packed bf16x2 words per h row  (128)
#define XW   (Fdim / 2)  // packed words per x row          (64)
#define XSTR (Tlen * XW) // x packed row stride per batch

// ---------------------------------------------------------------------------
// Persistent device scratch. ALL batch-indexed arrays use SORTED row order
// (rows sorted by length descending; perm maps sorted -> original).
// ---------------------------------------------------------------------------
__device__ uint32_t g_h1h[2][Bsz * HW];
__device__ uint32_t g_h1l[2][Bsz * HW];
__device__ uint32_t g_h2h[2][Bsz * HW];
__device__ uint32_t g_h2l[2][Bsz * HW];
__device__ float    g_c1[Bsz * Hdim];
__device__ float    g_c2[Bsz * Hdim];
__device__ float    g_sum[Bsz * Hdim];
__device__ int      g_perm[Bsz];      // sorted row -> original row
__device__ int      g_lenS[Bsz];      // sorted lengths (descending)
__device__ int      g_nbArr[Tlen];    // active row-block count per step (16/8/4)
__device__ int      g_tgt[Tlen];      // cumulative per-block arrival target
__device__ int      g_trans[Tlen];    // 1 if nb changed vs previous step
__device__ unsigned g_ctr[16];        // per-row-block local barrier counters
__device__ unsigned g_bar;            // global barrier counter (transitions)

// Pre-split x (SORTED rows): packed bf16x2 words, layout [srow][t][f/2].
__device__ uint32_t g_xh[Bsz * Tlen * XW];
__device__ uint32_t g_xl[Bsz * Tlen * XW];

// Weights: gate-interleaved cols (h*4+g), bf16 hi/lo split, FRAGMENT-ordered:
// per (32-col strip s, 32-wide chunk c32): 1024 words = [hl][ks2][r][lane][nt]
// Consecutive c32 blocks are contiguous, so a 64-wide chunk is one 2048-word
// contiguous region.
__device__ uint32_t g_W1f[32 * NC1_32 * 1024];
__device__ uint32_t g_W2f[32 * NC2_32 * 1024];
__device__ float    g_b1r[G4H];
__device__ float    g_b2r[G4H];

// ---------------------------------------------------------------------------
// helpers
// ---------------------------------------------------------------------------
__device__ __forceinline__ float bfr(float a) {
    return __bfloat162float(__float2bfloat16(a));
}
__device__ __forceinline__ uint32_t packbf(float e0, float e1) {
    uint32_t d;
    asm("cvt.rn.bf16x2.f32 %0, %1, %2;" : "=r"(d) : "f"(e1), "f"(e0));
    return d;
}
__device__ __forceinline__ void mma_bf16(float* c, const uint32_t* a,
                                         const uint32_t* b) {
    asm volatile(
        "mma.sync.aligned.m16n8k16.row.col.f32.bf16.bf16.f32 "
        "{%0,%1,%2,%3}, {%4,%5,%6,%7}, {%8,%9}, {%0,%1,%2,%3};"
        : "+f"(c[0]), "+f"(c[1]), "+f"(c[2]), "+f"(c[3])
        : "r"(a[0]), "r"(a[1]), "r"(a[2]), "r"(a[3]), "r"(b[0]), "r"(b[1]));
}

// ldmatrix x4: loads the full m16k16 A fragment (4 regs) in one op.
#define LDSM_X4(r0, r1, r2, r3, addr) \
    asm volatile("ldmatrix.sync.aligned.m8n8.x4.shared.b16 {%0,%1,%2,%3}, [%4];" \
        : "=r"(r0), "=r"(r1), "=r"(r2), "=r"(r3) : "r"(addr))

#define CPASYNC16(dst, src) \
    asm volatile("cp.async.ca.shared.global [%0], [%1], 16;" :: "r"(dst), "l"(src))
#define CPASYNC16CG(dst, src) \
    asm volatile("cp.async.cg.shared.global [%0], [%1], 16;" :: "r"(dst), "l"(src))
#define CP_COMMIT() asm volatile("cp.async.commit_group;")
#define CP_WAIT0()  asm volatile("cp.async.wait_group 0;")

__device__ __forceinline__ float fast_sig(float v)  { return 1.0f / (1.0f + __expf(-v)); }
__device__ __forceinline__ float fast_tanh(float v) { return 1.0f - 2.0f / (__expf(2.0f * v) + 1.0f); }

// ---------------------------------------------------------------------------
// Prolog 1: sort rows by length desc (bitonic, deterministic, idx asc ties),
// build perm/lenS, the per-step schedule nbArr, the cumulative local-barrier
// targets tgt[t] = sum_{t'<=t} 128/nb(t'), and transition flags.
// ---------------------------------------------------------------------------
__global__ void sort_kernel(const int* __restrict__ lengths)
{
    __shared__ unsigned key[Bsz];
    __shared__ int snb[Tlen];
    const int tid = threadIdx.x;       // 1024 threads
    key[tid]        = ((unsigned)(200 - lengths[tid]) << 11) | (unsigned)tid;
    key[tid + 1024] = ((unsigned)(200 - lengths[tid + 1024]) << 11)
                      | (unsigned)(tid + 1024);
    __syncthreads();
    for (int k = 2; k <= Bsz; k <<= 1) {
        for (int j = k >> 1; j > 0; j >>= 1) {
            const int i   = ((tid & ~(j - 1)) << 1) | (tid & (j - 1));
            const int par = i | j;
            const bool up = ((i & k) == 0);
            const unsigned a = key[i], b = key[par];
            if (up ? (a > b) : (a < b)) { key[i] = b; key[par] = a; }
            __syncthreads();
        }
    }
    for (int i = tid; i < Bsz; i += 1024) {
        g_perm[i] = (int)(key[i] & 2047u);
        g_lenS[i] = 200 - (int)(key[i] >> 11);
    }
    __syncthreads();
    if (tid < Tlen) {
        const unsigned thr = (unsigned)(200 - tid) << 11;
        int lo = 0, hi = Bsz;
        while (lo < hi) {
            const int mid = (lo + hi) >> 1;
            if (key[mid] < thr) lo = mid + 1; else hi = mid;
        }
        const int cb = (lo + 127) >> 7;            // ceil(R/128)
        int nb = 4;
        while (nb < cb) nb <<= 1;                  // pow2ceil, min 4
        if (nb > 16) nb = 16;
        g_nbArr[tid] = nb;
        snb[tid] = nb;
    }
    __syncthreads();
    if (tid < Tlen) {
        int acc = 0;
        for (int tt = 0; tt <= tid; tt++) acc += 128 / snb[tt];
        g_tgt[tid]   = acc;
        g_trans[tid] = (tid > 0 && snb[tid] != snb[tid - 1]) ? 1 : 0;
    }
}

// ---------------------------------------------------------------------------
// Prolog 2: split x into packed bf16x2 hi/lo, permuted into sorted row order.
// ---------------------------------------------------------------------------
__global__ void split_x_kernel(const float* __restrict__ x)
{
    const int n2 = Bsz * (XSTR / 2);   // uint2 elements per dest
    for (int i = blockIdx.x * blockDim.x + threadIdx.x; i < n2;
         i += gridDim.x * blockDim.x) {
        const int srow = i / (XSTR / 2);
        const int rem  = i % (XSTR / 2);
        const int orow = g_perm[srow];
        float4 v = ((const float4*)x)[(size_t)orow * (XSTR / 2) + rem];
        uint2 wh, wl;
        wh.x = packbf(v.x, v.y);
        wh.y = packbf(v.z, v.w);
        wl.x = packbf(v.x - bfr(v.x), v.y - bfr(v.y));
        wl.y = packbf(v.z - bfr(v.z), v.w - bfr(v.w));
        ((uint2*)g_xh)[i] = wh;
        ((uint2*)g_xl)[i] = wl;
    }
}

// ---------------------------------------------------------------------------
// Prolog 3: weight reorder into fragment order + bf16 hi/lo split.
// ---------------------------------------------------------------------------
__global__ void reorder_frag(const float* __restrict__ W,
                             const float* __restrict__ bias,
                             int NC, int which)
{
    uint32_t* Wf = which ? g_W2f : g_W1f;
    float*    bd = which ? g_b2r : g_b1r;
    const int n = 32 * NC * 1024;
    for (int idx = blockIdx.x * blockDim.x + threadIdx.x; idx < n;
         idx += gridDim.x * blockDim.x) {
        int nt   = idx & 3;
        int lane = (idx >> 2) & 31;
        int r    = (idx >> 7) & 1;
        int ks2  = (idx >> 8) & 1;
        int hl   = (idx >> 9) & 1;
        int sc   = idx >> 10;
        int c    = sc % NC;
        int s    = sc / NC;

        int k0  = c * 32 + ks2 * 16 + r * 8 + 2 * (lane & 3);
        int col = s * 32 + nt * 8 + (lane >> 2);
        int h = col >> 2, g = col & 3;
        float w0 = W[k0 * G4H + g * Hdim + h];
        float w1 = W[(k0 + 1) * G4H + g * Hdim + h];
        Wf[idx] = (hl == 0)
            ? packbf(w0, w1)
            : packbf(w0 - bfr(w0), w1 - bfr(w1));

        if (idx < G4H) {
            int hh = idx >> 2, gg = idx & 3;
            bd[idx] = bias[gg * Hdim + hh];
        }
    }
}

__global__ void zero_kernel()
{
    const int idx = blockIdx.x * blockDim.x + threadIdx.x;
    if (idx == 0) g_bar = 0u;
    if (idx < 16) g_ctr[idx] = 0u;
    if (idx < Bsz * Hdim) {
        g_c1[idx] = 0.f; g_c2[idx] = 0.f; g_sum[idx] = 0.f;
    }
    if (idx < Bsz * HW) {
        g_h1h[0][idx] = 0u; g_h1l[0][idx] = 0u;
        g_h2h[0][idx] = 0u; g_h2l[0][idx] = 0u;
        g_h1h[1][idx] = 0u; g_h1l[1][idx] = 0u;
        g_h2h[1][idx] = 0u; g_h2l[1][idx] = 0u;
    }
}

// ---------------------------------------------------------------------------
// One layer phase, templated on LAYER and NB (active row blocks: 16/8/4).
// KC=64 chunks (half the chunk boundaries of the KC=32 version; each compute
// phase now exceeds the cp.async fill latency so wait_group 0 rarely blocks),
// 2-stage double buffer (the proven-safe pipeline shape), ldmatrix A
// fragments, bf16 m16n8k16 3-term split GEMM in the SAME k-step order as the
// KC=32 kernel (numerically bit-identical), fused LSTM cell epilogue.
// c/sum state in gmem (.cg). Masked rows (past length) write nothing.
// ---------------------------------------------------------------------------
#define ASTR   36                  // 32 data words + 4 pad (144 B rows)
#define A_LO_W 4608                // 128 * 36
#define B_W    9216                // 2 * 4608
#define STGW   (B_W + 4 * 2048)    // 17408 words (B sized for STRN=4)
#define STGB   (STGW * 4)          // 69632 B per stage
#define SMEM_TOTAL (2 * STGB)      // 139264 B
#define ZSTR   132

template <int LAYER, int NB>
__device__ __forceinline__ void phase_fn(int t)
{
    constexpr int NC   = (LAYER == 1) ? 6 : 8;    // K/64
    constexpr int W0C  = (LAYER == 1) ? 2 : 4;    // 64-chunks from segment 0
    constexpr int NC32 = (LAYER == 1) ? NC1_32 : NC2_32;  // weight granularity
    constexpr int NT   = NB / 4;     // n8 tiles per warp
    constexpr int STRN = NB / 4;     // 32-col weight strips per CTA
    constexpr int WPS  = 4 / NT;     // warps sharing one strip
    constexpr int STRIPS = 128 / NB; // CTAs per row block
    constexpr int UPT  = NB / 2;     // units per epilogue thread

    extern __shared__ uint32_t smw[];
    uint32_t smb;
    asm("{ .reg .u64 t0; cvta.to.shared.u64 t0, %1; cvt.u32.u64 %0, t0; }"
        : "=r"(smb) : "l"(smw));

    const uint32_t* __restrict__ Wf = (LAYER == 1) ? g_W1f : g_W2f;
    const float*    __restrict__ bd = (LAYER == 1) ? g_b1r : g_b2r;
    float* __restrict__ cst = (LAYER == 1) ? g_c1 : g_c2;

    const int tid  = threadIdx.x;
    const int lane = tid & 31;
    const int gq   = lane >> 2;
    const int rq   = lane & 3;
    const int wid  = tid >> 5;
    const int wr   = wid & 3;
    const int wcol = wid >> 2;
    const int rb   = blockIdx.x / STRIPS;
    const int cs   = blockIdx.x % STRIPS;
    const int row0 = rb * 128;
    const int col0 = cs * (8 * NB);
    const int sbase = cs * STRN;
    const int prow = tid >> 2;
    const int pq   = tid & 3;
    const int erow = tid >> 2;
    const int eub  = (tid & 3) * UPT;

    const int p = t & 1;
    const uint32_t* s0h; const uint32_t* s0l; size_t s0s, s0k;
    if (LAYER == 1) { s0h = g_xh; s0l = g_xl; s0s = XSTR; s0k = (size_t)t * XW; }
    else            { s0h = g_h1h[p ^ 1]; s0l = g_h1l[p ^ 1]; s0s = HW; s0k = 0; }
    const uint32_t* hph = (LAYER == 1) ? g_h1h[p] : g_h2h[p];
    const uint32_t* hpl = (LAYER == 1) ? g_h1l[p] : g_h2l[p];
    uint32_t* hnh = (LAYER == 1) ? g_h1h[p ^ 1] : g_h2h[p ^ 1];
    uint32_t* hnl = (LAYER == 1) ? g_h1l[p ^ 1] : g_h2l[p ^ 1];

    // ---- epilogue ownership + state prefetch (hidden under GEMM) ----
    const int rowg  = row0 + erow;
    const int mylen = g_lenS[rowg];
    const bool valid = (t < mylen);
    const int gu0 = (col0 >> 2) + eub;
    float creg[UPT], sumr[UPT];
    if (valid) {
#pragma unroll
        for (int u = 0; u < UPT; u++) {
            creg[u] = __ldcg(&cst[rowg * Hdim + gu0 + u]);
            if (LAYER == 2) sumr[u] = __ldcg(&g_sum[rowg * Hdim + gu0 + u]);
        }
    }

    // ldmatrix lane address bases (per mt): row = wr*32 + mt*16 + (lane&15),
    // k-halves selected by (lane>>4)*16 bytes; ks adds 32 B per k16 substep.
    // Row stride 144 B keeps the 8 row addresses in distinct 16 B slots.
    uint32_t a_addr[2];
#pragma unroll
    for (int mt = 0; mt < 2; mt++)
        a_addr[mt] = smb
            + (uint32_t)((wr * 32 + mt * 16 + (lane & 15)) * ASTR * 4)
            + (uint32_t)((lane >> 4) * 16);

    auto fill = [&](int c) {
        const uint32_t sb = smb + (uint32_t)(c & 1) * STGB;
        size_t off; const uint32_t *ph, *pl;
        if (c < W0C) {
            ph = s0h; pl = s0l;
            off = (size_t)(row0 + prow) * s0s + s0k + c * 32 + pq * 8;
        } else {
            ph = hph; pl = hpl;
            off = (size_t)(row0 + prow) * HW + (c - W0C) * 32 + pq * 8;
        }
        // A: 2 x 16B hi + 2 x 16B lo per thread (row = 32 words = 8 quads)
        const uint32_t adst = sb + (uint32_t)(prow * ASTR + pq * 8) * 4u;
        CPASYNC16CG(adst, ph + off);                 // .cg: no stale L1
        CPASYNC16CG(adst + 16u, ph + off + 4);
        CPASYNC16CG(adst + A_LO_W * 4u, pl + off);
        CPASYNC16CG(adst + A_LO_W * 4u + 16u, pl + off + 4);
        // B: STRN strips x 2048 words (two contiguous c32 blocks per strip)
#pragma unroll
        for (int o = 0; o < STRN; o++) {
            const int oo = tid + o * 512;            // [0, STRN*512)
            const int j = oo >> 9;                   // strip
            const int w = (oo & 511) * 4;            // word within 2048
            const uint32_t* src =
                Wf + ((size_t)(sbase + j) * NC32 + 2 * c) * 1024 + w;
            CPASYNC16(sb + (uint32_t)(B_W + j * 2048 + w) * 4u, src);
        }
    };

    float acc[2][NT][4];
#pragma unroll
    for (int mt = 0; mt < 2; mt++)
#pragma unroll
        for (int nt = 0; nt < NT; nt++)
#pragma unroll
            for (int q = 0; q < 4; q++) acc[mt][nt][q] = 0.0f;

    fill(0);
    CP_COMMIT();

#pragma unroll 1
    for (int c = 0; c < NC; c++) {
        CP_WAIT0();            // chunk c landed
        __syncthreads();       // data published + prior compute done
        if (c + 1 < NC) { fill(c + 1); CP_COMMIT(); }

        const uint32_t soff = (uint32_t)(c & 1) * STGB;
        const uint32_t* bb  = smw + (c & 1) * STGW + B_W
                            + (wcol / WPS) * 2048 + (wcol % WPS) * NT;

#pragma unroll
        for (int ks = 0; ks < 4; ks++) {
            const int kb = (ks >> 1) * 1024 + (ks & 1) * 256;
            uint32_t bh0[NT], bh1[NT], bl0[NT], bl1[NT];
            if (NT == 4) {
                *(uint4*)bh0 = *(const uint4*)(bb + kb + lane * 4);
                *(uint4*)bh1 = *(const uint4*)(bb + kb + 128 + lane * 4);
                *(uint4*)bl0 = *(const uint4*)(bb + kb + 512 + lane * 4);
                *(uint4*)bl1 = *(const uint4*)(bb + kb + 512 + 128 + lane * 4);
            } else if (NT == 2) {
                *(uint2*)bh0 = *(const uint2*)(bb + kb + lane * 4);
                *(uint2*)bh1 = *(const uint2*)(bb + kb + 128 + lane * 4);
                *(uint2*)bl0 = *(const uint2*)(bb + kb + 512 + lane * 4);
                *(uint2*)bl1 = *(const uint2*)(bb + kb + 512 + 128 + lane * 4);
            } else {
                bh0[0] = bb[kb + lane * 4];
                bh1[0] = bb[kb + 128 + lane * 4];
                bl0[0] = bb[kb + 512 + lane * 4];
                bl1[0] = bb[kb + 512 + 128 + lane * 4];
            }

#pragma unroll
            for (int mt = 0; mt < 2; mt++) {
                uint32_t ah[4], al[4];
                const uint32_t ab = a_addr[mt] + soff + (uint32_t)(ks * 32);
                LDSM_X4(ah[0], ah[1], ah[2], ah[3], ab);
                LDSM_X4(al[0], al[1], al[2], al[3], ab + A_LO_W * 4u);
#pragma unroll
                for (int nt = 0; nt < NT; nt++) {
                    uint32_t bhp[2] = { bh0[nt], bh1[nt] };
                    uint32_t blp[2] = { bl0[nt], bl1[nt] };
                    mma_bf16(acc[mt][nt], ah, bhp);
                    mma_bf16(acc[mt][nt], ah, blp);
                    mma_bf16(acc[mt][nt], al, bhp);
                }
            }
        }
    }
    __syncthreads();   // all compute done before Z overwrites stages

    // ---- stage Z in smem ----
    float* Zs = (float*)smw;
#pragma unroll
    for (int mt = 0; mt < 2; mt++)
#pragma unroll
        for (int nt = 0; nt < NT; nt++) {
            const int row = wr * 32 + mt * 16 + gq;
            const int col = wcol * (8 * NT) + nt * 8 + 2 * rq;
            Zs[row * ZSTR + col]           = acc[mt][nt][0];
            Zs[row * ZSTR + col + 1]       = acc[mt][nt][1];
            Zs[(row + 8) * ZSTR + col]     = acc[mt][nt][2];
            Zs[(row + 8) * ZSTR + col + 1] = acc[mt][nt][3];
        }
    __syncthreads();

    // ---- fused LSTM cell (valid rows only) ----
    if (valid) {
        const size_t hw0 = (size_t)rowg * HW + (gu0 >> 1);
#pragma unroll
        for (int u2 = 0; u2 < UPT / 2; u2++) {
            float nhv[2];
#pragma unroll
            for (int e = 0; e < 2; e++) {
                const int uu = 2 * u2 + e;
                const int n4 = (eub + uu) * 4;
                float4 z  = *(const float4*)&Zs[erow * ZSTR + n4];
                float4 bv = *(const float4*)&bd[col0 + n4];
                const float zi = z.x + bv.x;
                const float zj = z.y + bv.y;
                const float zf = z.z + bv.z;
                const float zo = z.w + bv.w;
                const float nc = creg[uu] * fast_sig(zf + 1.0f)
                               + fast_sig(zi) * fast_tanh(zj);
                const float nh = fast_tanh(nc) * fast_sig(zo);
                creg[uu] = nc;
                if (LAYER == 2) sumr[uu] += nh;
                nhv[e] = nh;
            }
            hnh[hw0 + u2] = packbf(nhv[0], nhv[1]);
            hnl[hw0 + u2] = packbf(nhv[0] - bfr(nhv[0]),
                                   nhv[1] - bfr(nhv[1]));
        }
#pragma unroll
        for (int u = 0; u < UPT; u++) {
            __stcg(&cst[rowg * Hdim + gu0 + u], creg[u]);
            if (LAYER == 2) __stcg(&g_sum[rowg * Hdim + gu0 + u], sumr[u]);
        }
    }
    __syncthreads();   // Z reads done before next phase's fill
}

// ---------------------------------------------------------------------------
// Persistent kernel: 128 CTAs, 200 steps x 2 layers.
// Per-step LOCAL row-block barrier (128/nb CTAs); GLOBAL barrier only at
// nb transitions (<=2 per run), where the CTA<->block mapping changes.
// ---------------------------------------------------------------------------
__global__ void __launch_bounds__(512, 1)
lstm_persist()
{
    const int tid = threadIdx.x;
    int ntrans = 0;

#pragma unroll 1
    for (int t = 0; t < Tlen; t++) {
        const int nb = g_nbArr[t];

        // Global barrier at nb transitions: CTA->row-block mapping changes,
        // so the previous step's writers are a different CTA set.
        if (t > 0 && g_trans[t]) {
            ntrans++;
            if (tid == 0) {
                unsigned* bp = &g_bar;
                asm volatile("red.release.gpu.add.u32 [%0], 1;" :: "l"(bp) : "memory");
                const unsigned tgt = 128u * (unsigned)ntrans;
                unsigned v;
                while (true) {
                    asm volatile("ld.acquire.gpu.b32 %0, [%1];"
                                 : "=r"(v) : "l"(bp) : "memory");
                    if (v >= tgt) break;
                    asm volatile("nanosleep.u32 128;");
                }
            }
            __syncthreads();
        }

        if (nb == 16)     phase_fn<1, 16>(t);
        else if (nb == 8) phase_fn<1, 8>(t);
        else              phase_fn<1, 4>(t);

        // Local row-block barrier (128/nb CTAs), cumulative target g_tgt[t].
        {
            const int strips = 128 / nb;
            if (tid == 0) {
                unsigned* bp = &g_ctr[blockIdx.x / strips];
                asm volatile("red.release.gpu.add.u32 [%0], 1;" :: "l"(bp) : "memory");
                const unsigned tgt = (unsigned)g_tgt[t];
                unsigned v;
                while (true) {
                    asm volatile("ld.acquire.gpu.b32 %0, [%1];"
                                 : "=r"(v) : "l"(bp) : "memory");
                    if (v >= tgt) break;
                    asm volatile("nanosleep.u32 64;");
                }
            }
            __syncthreads();
        }

        if (nb == 16)     phase_fn<2, 16>(t);
        else if (nb == 8) phase_fn<2, 8>(t);
        else              phase_fn<2, 4>(t);
    }
}

// ---------------------------------------------------------------------------
// logits[orig b, o] = dot(sum_sorted[srow,:], Wout[:,o]) / lenS[srow] + bout[o]
// ---------------------------------------------------------------------------
__global__ void final_kernel(const float* __restrict__ Wout,
                             const float* __restrict__ bout,
                             float* __restrict__ out)
{
    const int idx = blockIdx.x * blockDim.x + threadIdx.x;
    if (idx >= Bsz * Odim) return;
    const int srow = idx / Odim;
    const int o    = idx % Odim;
    const float* s = g_sum + srow * Hdim;
    float acc = 0.0f;
#pragma unroll 8
    for (int h = 0; h < Hdim; h++) acc += s[h] * Wout[h * Odim + o];
    out[g_perm[srow] * Odim + o] =
        acc / (float)g_lenS[srow] + bout[o];
}

// ---------------------------------------------------------------------------
// Inputs (metadata order): x, lengths, W1, b1, W2, b2, Wout, bout
// ---------------------------------------------------------------------------
extern "C" void kernel_launch(void* const* d_in, const int* in_sizes, int n_in,
                              void* d_out, int out_size)
{
    const float* x       = (const float*)d_in[0];
    const int*   lengths = (const int*)d_in[1];
    const float* W1      = (const float*)d_in[2];
    const float* b1      = (const float*)d_in[3];
    const float* W2      = (const float*)d_in[4];
    const float* b2      = (const float*)d_in[5];
    const float* Wout    = (const float*)d_in[6];
    const float* bout    = (const float*)d_in[7];
    float* out = (float*)d_out;

    cudaFuncSetAttribute(lstm_persist,
                         cudaFuncAttributeMaxDynamicSharedMemorySize, SMEM_TOTAL);

    sort_kernel<<<1, 1024>>>(lengths);
    split_x_kernel<<<4096, 256>>>(x);
    reorder_frag<<<1536, 256>>>(W1, b1, NC1_32, 0);
    reorder_frag<<<2048, 256>>>(W2, b2, NC2_32, 1);
    zero_kernel<<<2048, 256>>>();

    lstm_persist<<<128, 512, SMEM_TOTAL>>>();

    final_kernel<<<(Bsz * Odim + 255) / 256, 256>>>(Wout, bout, out);
}